// round 9
// baseline (speedup 1.0000x reference)
#include <cuda_runtime.h>
#include <cstddef>

typedef unsigned long long u64t;

// ---- packed f32x2 helpers (sm_103a FFMA2) ----
__device__ __forceinline__ u64t pk2(float x) {
    u64t r; unsigned u = __float_as_uint(x);
    asm("mov.b64 %0, {%1, %1};" : "=l"(r) : "r"(u));
    return r;
}
__device__ __forceinline__ u64t ff2(u64t a, u64t b, u64t c) {
    u64t d;
    asm("fma.rn.f32x2 %0, %1, %2, %3;" : "=l"(d) : "l"(a), "l"(b), "l"(c));
    return d;
}
__device__ __forceinline__ float2 upk(u64t a) {
    unsigned lo, hi;
    asm("mov.b64 {%0, %1}, %2;" : "=r"(lo), "=r"(hi) : "l"(a));
    return make_float2(__uint_as_float(lo), __uint_as_float(hi));
}

#define BB   2
#define TT   512
#define BT   1024      // BB*TT rows
#define NH   16
#define FD   16
#define HD   64
#define HID  1024
#define DPHI 153
#define DPAD 160
#define CHK  64        // chunk length
#define NC   8         // chunks per sequence
#define NBH  32        // BB*NH
#define NTASK (NBH*NC) // 256 chunk tasks
#define EPSI 1e-12f

// ---- scratch (static __device__, no allocs) ----
__device__ float g_q[BT * NH * FD];              // [row][h*16+f]
__device__ float g_k[BT * NH * FD];
__device__ float g_v[BT * HID];                  // [row][h*64+d]
__device__ float g_y[BT * HID];                  // normalized attention out
__device__ float g_G[NTASK * DPAD * HD];         // per-chunk  phiK^T @ V
__device__ float g_S[NTASK * DPAD * HD];         // exclusive prefix of G
__device__ float g_cs[NTASK * DPAD];             // per-chunk colsum(phiK)
__device__ float g_Z[NTASK * DPAD];              // exclusive prefix of cs

// phi mapping: phi[D] = sc * x[pi] * x[pj], with x[16] := 1
__device__ __forceinline__ void phi_map(int D, int& pi, int& pj, float& sc)
{
    pi = 16; pj = 16; sc = 0.f;
    if (D == 0)        { sc = 1.f; }
    else if (D < 17)   { pi = D - 1;  sc = 0.5f; }
    else if (D < 33)   { pi = D - 17; pj = pi; sc = 0.17677669529663687f; }
    else if (D < DPHI) {
        int pp = D - 33, i = 0;
        while (pp >= 15 - i) { pp -= 15 - i; i++; }
        pi = i; pj = i + 1 + pp; sc = 0.25f;
    }
}

// ============================================================================
// Packed-FMA NT GEMM tile: 64(M) x 128(N), K=1024, 256 threads.
// Microtile 4x8: ty(16)x4 rows, tx(16)x(4+4) cols (two 128B-apart groups).
// Double-buffered smem; inner product via fma.rn.f32x2.
// A row-major [*,1024]; Bw row-major [*,1024] (N rows); C row-major ldc.
// ============================================================================
struct GSmem { float A[2][16][64]; float B[2][16][128]; };

__device__ __forceinline__ void gemm_tile(
    const float* __restrict__ A, const float* __restrict__ Bw,
    float* __restrict__ C, int ldc)
{
    __shared__ GSmem sm;
    const int tid = threadIdx.x;
    const int tx = tid & 15, ty = tid >> 4;
    const int arow = tid >> 2, akq = (tid & 3) << 2;   // A: 1 float4/thread
    const int bn = tid >> 1,  bkh = (tid & 1) << 3;    // B: 2 float4/thread

    const float* Ap = A  + (size_t)arow * HID + akq;
    const float* Bp = Bw + (size_t)bn   * HID + bkh;

    // prologue: tile 0
    float4 a4  = *(const float4*)Ap;
    float4 b40 = *(const float4*)Bp;
    float4 b41 = *(const float4*)(Bp + 4);
    sm.A[0][akq + 0][arow] = a4.x;  sm.A[0][akq + 1][arow] = a4.y;
    sm.A[0][akq + 2][arow] = a4.z;  sm.A[0][akq + 3][arow] = a4.w;
    sm.B[0][bkh + 0][bn] = b40.x;   sm.B[0][bkh + 1][bn] = b40.y;
    sm.B[0][bkh + 2][bn] = b40.z;   sm.B[0][bkh + 3][bn] = b40.w;
    sm.B[0][bkh + 4][bn] = b41.x;   sm.B[0][bkh + 5][bn] = b41.y;
    sm.B[0][bkh + 6][bn] = b41.z;   sm.B[0][bkh + 7][bn] = b41.w;
    __syncthreads();

    u64t acc[4][4];
#pragma unroll
    for (int i = 0; i < 4; i++)
#pragma unroll
        for (int j = 0; j < 4; j++) acc[i][j] = 0ull;

#pragma unroll 1
    for (int t = 0; t < HID / 16; t++) {
        const int cur = t & 1;
        if (t + 1 < HID / 16) {
            a4  = *(const float4*)(Ap + (t + 1) * 16);
            b40 = *(const float4*)(Bp + (t + 1) * 16);
            b41 = *(const float4*)(Bp + (t + 1) * 16 + 4);
        }
#pragma unroll
        for (int kk = 0; kk < 16; kk++) {
            float4 av = *(const float4*)&sm.A[cur][kk][ty << 2];
            ulonglong2 b0 = *(const ulonglong2*)&sm.B[cur][kk][tx << 2];
            ulonglong2 b1 = *(const ulonglong2*)&sm.B[cur][kk][64 + (tx << 2)];
            u64t p0 = pk2(av.x), p1 = pk2(av.y), p2 = pk2(av.z), p3 = pk2(av.w);
            acc[0][0] = ff2(p0, b0.x, acc[0][0]);
            acc[0][1] = ff2(p0, b0.y, acc[0][1]);
            acc[0][2] = ff2(p0, b1.x, acc[0][2]);
            acc[0][3] = ff2(p0, b1.y, acc[0][3]);
            acc[1][0] = ff2(p1, b0.x, acc[1][0]);
            acc[1][1] = ff2(p1, b0.y, acc[1][1]);
            acc[1][2] = ff2(p1, b1.x, acc[1][2]);
            acc[1][3] = ff2(p1, b1.y, acc[1][3]);
            acc[2][0] = ff2(p2, b0.x, acc[2][0]);
            acc[2][1] = ff2(p2, b0.y, acc[2][1]);
            acc[2][2] = ff2(p2, b1.x, acc[2][2]);
            acc[2][3] = ff2(p2, b1.y, acc[2][3]);
            acc[3][0] = ff2(p3, b0.x, acc[3][0]);
            acc[3][1] = ff2(p3, b0.y, acc[3][1]);
            acc[3][2] = ff2(p3, b1.x, acc[3][2]);
            acc[3][3] = ff2(p3, b1.y, acc[3][3]);
        }
        if (t + 1 < HID / 16) {
            const int nxt = cur ^ 1;
            sm.A[nxt][akq + 0][arow] = a4.x;  sm.A[nxt][akq + 1][arow] = a4.y;
            sm.A[nxt][akq + 2][arow] = a4.z;  sm.A[nxt][akq + 3][arow] = a4.w;
            sm.B[nxt][bkh + 0][bn] = b40.x;   sm.B[nxt][bkh + 1][bn] = b40.y;
            sm.B[nxt][bkh + 2][bn] = b40.z;   sm.B[nxt][bkh + 3][bn] = b40.w;
            sm.B[nxt][bkh + 4][bn] = b41.x;   sm.B[nxt][bkh + 5][bn] = b41.y;
            sm.B[nxt][bkh + 6][bn] = b41.z;   sm.B[nxt][bkh + 7][bn] = b41.w;
        }
        __syncthreads();
    }

#pragma unroll
    for (int i = 0; i < 4; i++) {
        float2 c0 = upk(acc[i][0]), c1 = upk(acc[i][1]);
        float2 c2 = upk(acc[i][2]), c3 = upk(acc[i][3]);
        float* Cp = C + (size_t)((ty << 2) + i) * ldc;
        *(float4*)&Cp[tx << 2]        = make_float4(c0.x, c0.y, c1.x, c1.y);
        *(float4*)&Cp[64 + (tx << 2)] = make_float4(c2.x, c2.y, c3.x, c3.y);
    }
}

// fused q/k/v projections: grid (12, 16). bx<2: q, bx<4: k, else v.
__global__ __launch_bounds__(256) void proj_gemm(
    const float* __restrict__ hs, const float* __restrict__ Wq,
    const float* __restrict__ Wk, const float* __restrict__ Wv)
{
    const int bx = blockIdx.x, by = blockIdx.y;
    const float* Bw; float* C; int ldc, n0;
    if (bx < 2)      { Bw = Wq; C = g_q; ldc = NH * FD; n0 = bx * 128; }
    else if (bx < 4) { Bw = Wk; C = g_k; ldc = NH * FD; n0 = (bx - 2) * 128; }
    else             { Bw = Wv; C = g_v; ldc = HID;     n0 = (bx - 4) * 128; }
    gemm_tile(hs + (size_t)by * 64 * HID, Bw + (size_t)n0 * HID,
              C + (size_t)by * 64 * ldc + n0, ldc);
}

// output projection: grid (8, 16)
__global__ __launch_bounds__(256) void out_gemm(
    const float* __restrict__ Wo, float* __restrict__ out)
{
    gemm_tile(g_y + (size_t)blockIdx.y * 64 * HID,
              Wo + (size_t)blockIdx.x * 128 * HID,
              out + (size_t)blockIdx.y * 64 * HID + blockIdx.x * 128, HID);
}

// ============================================================================
// Kernel A: per chunk, G = phiK^T @ V  (DPAD x HD) and colsum(phiK).
// ============================================================================
struct SmemA {
    float P[DPAD][68];
    float V[CHK][68];
    float R[CHK][17];
};

__global__ __launch_bounds__(256) void chunk_outer()
{
    extern __shared__ float sm_raw[];
    SmemA* s = (SmemA*)sm_raw;
    const int task = blockIdx.x;
    const int bh = task >> 3, c = task & 7;
    const int b = bh >> 4, h = bh & 15, t0 = c * CHK;
    const int tid = threadIdx.x;

    for (int e = tid; e < CHK * FD; e += 256) {
        int t = e >> 4, f = e & 15;
        s->R[t][f] = g_k[((size_t)(b * TT + t0 + t)) * (NH * FD) + h * FD + f];
    }
    if (tid < CHK) s->R[tid][16] = 1.f;
    for (int e = tid; e < CHK * 16; e += 256) {
        int t = e >> 4, d4 = (e & 15) << 2;
        *(float4*)&s->V[t][d4] =
            *(const float4*)&g_v[((size_t)(b * TT + t0 + t)) * HID + h * HD + d4];
    }
    __syncthreads();

    if (tid < DPAD) {
        int pi, pj; float sc;
        phi_map(tid, pi, pj, sc);
#pragma unroll 4
        for (int t = 0; t < CHK; t++)
            s->P[tid][t] = sc * s->R[t][pi] * s->R[t][pj];
    }
    __syncthreads();

    const int tx = tid & 15, ty = tid >> 4;
    u64t accp[10][2];
#pragma unroll
    for (int r = 0; r < 10; r++) { accp[r][0] = 0ull; accp[r][1] = 0ull; }

    for (int t = 0; t < CHK; t++) {
        ulonglong2 v2 = *(const ulonglong2*)&s->V[t][tx << 2];
#pragma unroll
        for (int r = 0; r < 10; r++) {
            u64t pp = pk2(s->P[ty * 10 + r][t]);
            accp[r][0] = ff2(pp, v2.x, accp[r][0]);
            accp[r][1] = ff2(pp, v2.y, accp[r][1]);
        }
    }

    float* Gp = g_G + (size_t)task * (DPAD * HD);
#pragma unroll
    for (int r = 0; r < 10; r++) {
        float2 c0 = upk(accp[r][0]), c1 = upk(accp[r][1]);
        *(float4*)&Gp[(ty * 10 + r) * HD + (tx << 2)] =
            make_float4(c0.x, c0.y, c1.x, c1.y);
    }

    if (tid < DPAD) {
        float cs = 0.f;
#pragma unroll 4
        for (int t = 0; t < CHK; t++) cs += s->P[tid][t];
        g_cs[(size_t)task * DPAD + tid] = cs;
    }
}

// ============================================================================
// Kernel B: exclusive prefix over chunks. grid (NBH, 8): z slices e-range.
// ============================================================================
__global__ __launch_bounds__(256) void prefix_kernel()
{
    const int bh = blockIdx.x, z = blockIdx.y;
    const int tid = threadIdx.x;
    const size_t base = (size_t)bh * NC;
    const int e0 = z * (DPAD * HD / 8), e1 = e0 + (DPAD * HD / 8);

    for (int e = e0 + tid; e < e1; e += 256) {
        float carry = 0.f;
#pragma unroll
        for (int c = 0; c < NC; c++) {
            size_t idx = (base + c) * (DPAD * HD) + e;
            float v = g_G[idx];
            g_S[idx] = carry;
            carry += v;
        }
    }
    if (z == 0) {
        for (int e = tid; e < DPAD; e += 256) {
            float carry = 0.f;
#pragma unroll
            for (int c = 0; c < NC; c++) {
                size_t idx = (base + c) * DPAD + e;
                float v = g_cs[idx];
                g_Z[idx] = carry;
                carry += v;
            }
        }
    }
}

// ============================================================================
// Kernel C: intra-chunk attention + inter-chunk state, normalized output.
// ============================================================================
struct SmemC {
    float Q[DPAD][68];
    float K[DPAD][68];
    float A[CHK][68];
    float V[CHK][68];
    float RQ[CHK][17];
    float RK[CHK][17];
    float Den[CHK];
    float Di[CHK];
};

__global__ __launch_bounds__(256) void attn_chunk()
{
    extern __shared__ float sm_raw[];
    SmemC* s = (SmemC*)sm_raw;
    const int task = blockIdx.x;
    const int bh = task >> 3, c = task & 7;
    const int b = bh >> 4, h = bh & 15, t0 = c * CHK;
    const int tid = threadIdx.x;

    for (int e = tid; e < CHK * FD; e += 256) {
        int t = e >> 4, f = e & 15;
        size_t row = (size_t)(b * TT + t0 + t);
        s->RQ[t][f] = g_q[row * (NH * FD) + h * FD + f];
        s->RK[t][f] = g_k[row * (NH * FD) + h * FD + f];
    }
    if (tid < CHK) { s->RQ[tid][16] = 1.f; s->RK[tid][16] = 1.f; }
    for (int e = tid; e < CHK * 16; e += 256) {
        int t = e >> 4, d4 = (e & 15) << 2;
        *(float4*)&s->V[t][d4] =
            *(const float4*)&g_v[((size_t)(b * TT + t0 + t)) * HID + h * HD + d4];
    }
    __syncthreads();

    if (tid < DPAD) {
        int pi, pj; float sc;
        phi_map(tid, pi, pj, sc);
#pragma unroll 4
        for (int t = 0; t < CHK; t++) {
            s->Q[tid][t] = sc * s->RQ[t][pi] * s->RQ[t][pj];
            s->K[tid][t] = sc * s->RK[t][pi] * s->RK[t][pj];
        }
    }
    __syncthreads();

    const int tx = tid & 15, ty = tid >> 4;

    // ---- phase 1: A = phiQ @ phiK^T (packed) ----
    u64t ap[4][2];
#pragma unroll
    for (int i = 0; i < 4; i++) { ap[i][0] = 0ull; ap[i][1] = 0ull; }

#pragma unroll 4
    for (int k = 0; k < DPAD; k++) {
        float4 qa = *(const float4*)&s->Q[k][ty << 2];
        ulonglong2 kb = *(const ulonglong2*)&s->K[k][tx << 2];
        u64t p0 = pk2(qa.x), p1 = pk2(qa.y), p2 = pk2(qa.z), p3 = pk2(qa.w);
        ap[0][0] = ff2(p0, kb.x, ap[0][0]); ap[0][1] = ff2(p0, kb.y, ap[0][1]);
        ap[1][0] = ff2(p1, kb.x, ap[1][0]); ap[1][1] = ff2(p1, kb.y, ap[1][1]);
        ap[2][0] = ff2(p2, kb.x, ap[2][0]); ap[2][1] = ff2(p2, kb.y, ap[2][1]);
        ap[3][0] = ff2(p3, kb.x, ap[3][0]); ap[3][1] = ff2(p3, kb.y, ap[3][1]);
    }

    float a[4][4];
#pragma unroll
    for (int i = 0; i < 4; i++) {
        float2 lo = upk(ap[i][0]), hi = upk(ap[i][1]);
        a[i][0] = lo.x; a[i][1] = lo.y; a[i][2] = hi.x; a[i][3] = hi.y;
    }

    // ---- mask + store A + intra denom rowsums ----
    float p[4] = {0.f, 0.f, 0.f, 0.f};
#pragma unroll
    for (int i = 0; i < 4; i++) {
        int trow = (ty << 2) + i;
        float4 m;
        m.x = ((tx << 2) + 0 <= trow) ? a[i][0] : 0.f;
        m.y = ((tx << 2) + 1 <= trow) ? a[i][1] : 0.f;
        m.z = ((tx << 2) + 2 <= trow) ? a[i][2] : 0.f;
        m.w = ((tx << 2) + 3 <= trow) ? a[i][3] : 0.f;
        *(float4*)&s->A[trow][tx << 2] = m;
        p[i] = m.x + m.y + m.z + m.w;
    }
#pragma unroll
    for (int i = 0; i < 4; i++) {
        p[i] += __shfl_xor_sync(0xffffffffu, p[i], 1);
        p[i] += __shfl_xor_sync(0xffffffffu, p[i], 2);
        p[i] += __shfl_xor_sync(0xffffffffu, p[i], 4);
        p[i] += __shfl_xor_sync(0xffffffffu, p[i], 8);
    }
    if (tx == 0) {
#pragma unroll
        for (int i = 0; i < 4; i++) s->Den[(ty << 2) + i] = p[i];
    }

    // ---- inter denom: phiQ_t . Z ----
    if (tid < CHK) {
        const float* Zp = g_Z + (size_t)task * DPAD;
        float di = 0.f;
#pragma unroll 4
        for (int k = 0; k < DPAD; k++)
            di = fmaf(s->Q[k][tid], __ldg(&Zp[k]), di);
        s->Di[tid] = di;
    }
    __syncthreads();

    // ---- phase 2: y = tril(A) @ V + phiQ @ S (packed) ----
    u64t yp[4][2];
#pragma unroll
    for (int i = 0; i < 4; i++) { yp[i][0] = 0ull; yp[i][1] = 0ull; }

#pragma unroll 4
    for (int k = 0; k < CHK; k++) {
        ulonglong2 v2 = *(const ulonglong2*)&s->V[k][tx << 2];
        u64t p0 = pk2(s->A[(ty << 2) + 0][k]);
        u64t p1 = pk2(s->A[(ty << 2) + 1][k]);
        u64t p2 = pk2(s->A[(ty << 2) + 2][k]);
        u64t p3 = pk2(s->A[(ty << 2) + 3][k]);
        yp[0][0] = ff2(p0, v2.x, yp[0][0]); yp[0][1] = ff2(p0, v2.y, yp[0][1]);
        yp[1][0] = ff2(p1, v2.x, yp[1][0]); yp[1][1] = ff2(p1, v2.y, yp[1][1]);
        yp[2][0] = ff2(p2, v2.x, yp[2][0]); yp[2][1] = ff2(p2, v2.y, yp[2][1]);
        yp[3][0] = ff2(p3, v2.x, yp[3][0]); yp[3][1] = ff2(p3, v2.y, yp[3][1]);
    }

    const float* Sp = g_S + (size_t)task * (DPAD * HD);
#pragma unroll 4
    for (int k = 0; k < DPAD; k++) {
        ulonglong2 s2 = *(const ulonglong2*)&Sp[k * HD + (tx << 2)];
        float4 q4 = *(const float4*)&s->Q[k][ty << 2];
        u64t p0 = pk2(q4.x), p1 = pk2(q4.y), p2 = pk2(q4.z), p3 = pk2(q4.w);
        yp[0][0] = ff2(p0, s2.x, yp[0][0]); yp[0][1] = ff2(p0, s2.y, yp[0][1]);
        yp[1][0] = ff2(p1, s2.x, yp[1][0]); yp[1][1] = ff2(p1, s2.y, yp[1][1]);
        yp[2][0] = ff2(p2, s2.x, yp[2][0]); yp[2][1] = ff2(p2, s2.y, yp[2][1]);
        yp[3][0] = ff2(p3, s2.x, yp[3][0]); yp[3][1] = ff2(p3, s2.y, yp[3][1]);
    }

    // ---- normalize + write ----
#pragma unroll
    for (int i = 0; i < 4; i++) {
        int trow = (ty << 2) + i;
        float dn = 1.f / (s->Den[trow] + s->Di[trow] + EPSI);
        float2 lo = upk(yp[i][0]), hi = upk(yp[i][1]);
        float4 o = make_float4(lo.x * dn, lo.y * dn, hi.x * dn, hi.y * dn);
        *(float4*)&g_y[((size_t)(b * TT + t0 + trow)) * HID + h * HD + (tx << 2)] = o;
    }
}

// ============================================================================
// kernel_launch
// ============================================================================
extern "C" void kernel_launch(void* const* d_in, const int* in_sizes, int n_in,
                              void* d_out, int out_size)
{
    const float* hs = (const float*)d_in[0];
    const float* Wq = (const float*)d_in[1];
    const float* Wk = (const float*)d_in[2];
    const float* Wv = (const float*)d_in[3];
    const float* Wo = (const float*)d_in[4];
    float* out = (float*)d_out;

    const int smemA = (int)sizeof(SmemA);
    const int smemC = (int)sizeof(SmemC);
    cudaFuncSetAttribute(chunk_outer, cudaFuncAttributeMaxDynamicSharedMemorySize, smemA);
    cudaFuncSetAttribute(attn_chunk,  cudaFuncAttributeMaxDynamicSharedMemorySize, smemC);

    // fused q/k/v projections (packed-FMA GEMM)
    proj_gemm<<<dim3(12, 16), 256>>>(hs, Wq, Wk, Wv);

    // chunked causal linear attention
    chunk_outer<<<NTASK, 256, smemA>>>();
    prefix_kernel<<<dim3(NBH, 8), 256>>>();
    attn_chunk<<<NTASK, 256, smemC>>>();

    // output projection
    out_gemm<<<dim3(8, 16), 256>>>(Wo, out);
}

// round 12
// speedup vs baseline: 2.0821x; 2.0821x over previous
#include <cuda_runtime.h>
#include <cuda_bf16.h>
#include <cstdint>
#include <cstddef>

#define BB   2
#define TT   512
#define BT   1024
#define NH   16
#define FD   16
#define HD   64
#define HID  1024
#define DPHI 153
#define DPAD 160
#define CHK  64
#define NC   8
#define NBH  32
#define NTASK (NBH*NC)
#define EPSI 1e-12f

// ---- scratch ----
__device__ float g_q[BT * NH * FD];
__device__ float g_k[BT * NH * FD];
__device__ float g_v[BT * HID];
__device__ float g_y[BT * HID];
__device__ float g_G[NTASK * DPAD * HD];
__device__ float g_S[NTASK * DPAD * HD];
__device__ float g_cs[NTASK * DPAD];
__device__ float g_Z[NTASK * DPAD];

// bf16 split buffers
__device__ __nv_bfloat16 g_hsh[BT * HID];
__device__ __nv_bfloat16 g_hsl[BT * HID];
__device__ __nv_bfloat16 g_yh[BT * HID];
__device__ __nv_bfloat16 g_yl[BT * HID];
// weights packed rows: [0,256)=Wq, [256,512)=Wk, [512,1536)=Wv, [1536,2560)=Wo
#define WROWS 2560
__device__ __nv_bfloat16 g_wh[WROWS * HID];
__device__ __nv_bfloat16 g_wl[WROWS * HID];

__device__ __forceinline__ uint32_t s2u(const void* p) {
    uint32_t a;
    asm("{ .reg .u64 t; cvta.to.shared.u64 t, %1; cvt.u32.u64 %0, t; }"
        : "=r"(a) : "l"(p));
    return a;
}
__device__ __forceinline__ void ldm4(uint32_t& r0, uint32_t& r1,
                                     uint32_t& r2, uint32_t& r3, uint32_t a) {
    asm volatile("ldmatrix.sync.aligned.m8n8.x4.shared.b16 {%0,%1,%2,%3}, [%4];"
                 : "=r"(r0), "=r"(r1), "=r"(r2), "=r"(r3) : "r"(a));
}
__device__ __forceinline__ void mma16816(float* c, const uint32_t* a,
                                         const uint32_t* b) {
    asm volatile(
        "mma.sync.aligned.m16n8k16.row.col.f32.bf16.bf16.f32 "
        "{%0,%1,%2,%3}, {%4,%5,%6,%7}, {%8,%9}, {%0,%1,%2,%3};"
        : "+f"(c[0]), "+f"(c[1]), "+f"(c[2]), "+f"(c[3])
        : "r"(a[0]), "r"(a[1]), "r"(a[2]), "r"(a[3]), "r"(b[0]), "r"(b[1]));
}

// ============================================================================
// bf16-split conversion kernels
// ============================================================================
__global__ __launch_bounds__(256) void conv_x(
    const float* __restrict__ src, __nv_bfloat16* __restrict__ dh,
    __nv_bfloat16* __restrict__ dl)
{
    size_t base = (size_t)blockIdx.x * 1024 + threadIdx.x * 4;
    float4 x = *(const float4*)(src + base);
    __nv_bfloat16 h0 = __float2bfloat16(x.x), h1 = __float2bfloat16(x.y);
    __nv_bfloat16 h2 = __float2bfloat16(x.z), h3 = __float2bfloat16(x.w);
    __nv_bfloat16 l0 = __float2bfloat16(x.x - __bfloat162float(h0));
    __nv_bfloat16 l1 = __float2bfloat16(x.y - __bfloat162float(h1));
    __nv_bfloat16 l2 = __float2bfloat16(x.z - __bfloat162float(h2));
    __nv_bfloat16 l3 = __float2bfloat16(x.w - __bfloat162float(h3));
    __nv_bfloat162* H = (__nv_bfloat162*)(dh + base);
    __nv_bfloat162* L = (__nv_bfloat162*)(dl + base);
    H[0] = __nv_bfloat162(h0, h1); H[1] = __nv_bfloat162(h2, h3);
    L[0] = __nv_bfloat162(l0, l1); L[1] = __nv_bfloat162(l2, l3);
}

__global__ __launch_bounds__(256) void conv_w(
    const float* __restrict__ Wq, const float* __restrict__ Wk,
    const float* __restrict__ Wv, const float* __restrict__ Wo)
{
    const int r = blockIdx.x;
    const float* src;
    if (r < 256)       src = Wq + (size_t)r * HID;
    else if (r < 512)  src = Wk + (size_t)(r - 256) * HID;
    else if (r < 1536) src = Wv + (size_t)(r - 512) * HID;
    else               src = Wo + (size_t)(r - 1536) * HID;
    size_t base = (size_t)r * HID + threadIdx.x * 4;
    float4 x = *(const float4*)(src + threadIdx.x * 4);
    __nv_bfloat16 h0 = __float2bfloat16(x.x), h1 = __float2bfloat16(x.y);
    __nv_bfloat16 h2 = __float2bfloat16(x.z), h3 = __float2bfloat16(x.w);
    __nv_bfloat16 l0 = __float2bfloat16(x.x - __bfloat162float(h0));
    __nv_bfloat16 l1 = __float2bfloat16(x.y - __bfloat162float(h1));
    __nv_bfloat16 l2 = __float2bfloat16(x.z - __bfloat162float(h2));
    __nv_bfloat16 l3 = __float2bfloat16(x.w - __bfloat162float(h3));
    __nv_bfloat162* H = (__nv_bfloat162*)(g_wh + base);
    __nv_bfloat162* L = (__nv_bfloat162*)(g_wl + base);
    H[0] = __nv_bfloat162(h0, h1); H[1] = __nv_bfloat162(h2, h3);
    L[0] = __nv_bfloat162(l0, l1); L[1] = __nv_bfloat162(l2, l3);
}

// ============================================================================
// mma.sync bf16-split GEMM: C[128,128] tile = A[128,1024] @ B[128,1024]^T
// D = AhBh + AhBl + AlBh, fp32 register accumulators.
// 256 threads = 8 warps (2M x 4N), warp tile 64x32, BK=32, smem rows 80B.
// ============================================================================
#define SROW 40   // bf16 elems per smem row (80 bytes)

__device__ void mm128_core(
    const __nv_bfloat16* __restrict__ Ah, const __nv_bfloat16* __restrict__ Al,
    const __nv_bfloat16* __restrict__ Bh, const __nv_bfloat16* __restrict__ Bl,
    float* __restrict__ C, int ldc)
{
    __shared__ __align__(16) __nv_bfloat16 sAh[128 * SROW];
    __shared__ __align__(16) __nv_bfloat16 sAl[128 * SROW];
    __shared__ __align__(16) __nv_bfloat16 sBh[128 * SROW];
    __shared__ __align__(16) __nv_bfloat16 sBl[128 * SROW];

    const int tid = threadIdx.x;
    const int wid = tid >> 5, lane = tid & 31;
    const int warpM = (wid >> 2) * 64;   // 0 or 64
    const int warpN = (wid & 3) * 32;    // 0,32,64,96

    // ldmatrix lane->address components
    const int lt = lane >> 3, lr = lane & 7;
    const int aRow = lr + (lt & 1) * 8;         // A: tiles (m0,k0),(m8,k0),(m0,k8),(m8,k8)
    const int aByte = (lt >> 1) * 16;
    const int bRow = lr + (lt >> 1) * 8;        // B: tiles (n0,k0),(n0,k8),(n8,k0),(n8,k8)
    const int bByte = (lt & 1) * 16;

    const uint32_t uAh = s2u(sAh), uAl = s2u(sAl);
    const uint32_t uBh = s2u(sBh), uBl = s2u(sBl);

    // gmem->smem mapping: 512 chunks of 16B per array; thread does tid, tid+256
    const int r0c = tid >> 2, q0 = (tid & 3) * 8;          // chunk tid
    const int r1c = (tid + 256) >> 2, q1 = ((tid + 256) & 3) * 8;

    float acc[4][4][4];
#pragma unroll
    for (int i = 0; i < 4; i++)
#pragma unroll
        for (int j = 0; j < 4; j++)
#pragma unroll
            for (int e = 0; e < 4; e++) acc[i][j][e] = 0.f;

    for (int kc = 0; kc < HID / 32; kc++) {
        const int kb = kc * 32;
        // load 4 tiles 128x32 bf16
        {
            uint4 vA0 = *(const uint4*)(Ah + (size_t)r0c * HID + kb + q0);
            uint4 vA1 = *(const uint4*)(Ah + (size_t)r1c * HID + kb + q1);
            uint4 wA0 = *(const uint4*)(Al + (size_t)r0c * HID + kb + q0);
            uint4 wA1 = *(const uint4*)(Al + (size_t)r1c * HID + kb + q1);
            uint4 vB0 = *(const uint4*)(Bh + (size_t)r0c * HID + kb + q0);
            uint4 vB1 = *(const uint4*)(Bh + (size_t)r1c * HID + kb + q1);
            uint4 wB0 = *(const uint4*)(Bl + (size_t)r0c * HID + kb + q0);
            uint4 wB1 = *(const uint4*)(Bl + (size_t)r1c * HID + kb + q1);
            __syncthreads();   // previous iter's reads done before overwrite
            *(uint4*)(sAh + r0c * SROW + q0) = vA0;
            *(uint4*)(sAh + r1c * SROW + q1) = vA1;
            *(uint4*)(sAl + r0c * SROW + q0) = wA0;
            *(uint4*)(sAl + r1c * SROW + q1) = wA1;
            *(uint4*)(sBh + r0c * SROW + q0) = vB0;
            *(uint4*)(sBh + r1c * SROW + q1) = vB1;
            *(uint4*)(sBl + r0c * SROW + q0) = wB0;
            *(uint4*)(sBl + r1c * SROW + q1) = wB1;
        }
        __syncthreads();

#pragma unroll
        for (int s = 0; s < 2; s++) {
            const int sb = s * 32;
            uint32_t ah[4][4], bh[4][2], bl[4][2], al[4][4];

            // Ah fragments (4 m16 tiles)
#pragma unroll
            for (int mi = 0; mi < 4; mi++)
                ldm4(ah[mi][0], ah[mi][1], ah[mi][2], ah[mi][3],
                     uAh + (warpM + mi * 16 + aRow) * 80 + sb + aByte);
            // Bh fragments (2 x 16n)
#pragma unroll
            for (int g = 0; g < 2; g++)
                ldm4(bh[2 * g][0], bh[2 * g][1], bh[2 * g + 1][0], bh[2 * g + 1][1],
                     uBh + (warpN + g * 16 + bRow) * 80 + sb + bByte);
#pragma unroll
            for (int mi = 0; mi < 4; mi++)
#pragma unroll
                for (int ng = 0; ng < 4; ng++)
                    mma16816(acc[mi][ng], ah[mi], bh[ng]);

            // Bl fragments; Ah x Bl
#pragma unroll
            for (int g = 0; g < 2; g++)
                ldm4(bl[2 * g][0], bl[2 * g][1], bl[2 * g + 1][0], bl[2 * g + 1][1],
                     uBl + (warpN + g * 16 + bRow) * 80 + sb + bByte);
#pragma unroll
            for (int mi = 0; mi < 4; mi++)
#pragma unroll
                for (int ng = 0; ng < 4; ng++)
                    mma16816(acc[mi][ng], ah[mi], bl[ng]);

            // Al fragments; Al x Bh
#pragma unroll
            for (int mi = 0; mi < 4; mi++)
                ldm4(al[mi][0], al[mi][1], al[mi][2], al[mi][3],
                     uAl + (warpM + mi * 16 + aRow) * 80 + sb + aByte);
#pragma unroll
            for (int mi = 0; mi < 4; mi++)
#pragma unroll
                for (int ng = 0; ng < 4; ng++)
                    mma16816(acc[mi][ng], al[mi], bh[ng]);
        }
    }

    // epilogue: c frag rows = lane>>2 (+8), cols = (lane&3)*2
    const int cr = lane >> 2, cc = (lane & 3) * 2;
#pragma unroll
    for (int mi = 0; mi < 4; mi++) {
#pragma unroll
        for (int ng = 0; ng < 4; ng++) {
            float* cp0 = C + (size_t)(warpM + mi * 16 + cr) * ldc
                           + warpN + ng * 8 + cc;
            float* cp1 = cp0 + 8 * ldc;
            cp0[0] = acc[mi][ng][0]; cp0[1] = acc[mi][ng][1];
            cp1[0] = acc[mi][ng][2]; cp1[1] = acc[mi][ng][3];
        }
    }
}

// fused q/k/v projections: grid (12, 8); wbase = bx*128 (packed rows)
__global__ __launch_bounds__(256) void proj_mm()
{
    const int bx = blockIdx.x, by = blockIdx.y;
    float* C; int ldc, n0;
    if (bx < 2)      { C = g_q; ldc = NH * FD; n0 = bx * 128; }
    else if (bx < 4) { C = g_k; ldc = NH * FD; n0 = (bx - 2) * 128; }
    else             { C = g_v; ldc = HID;     n0 = (bx - 4) * 128; }
    const size_t ao = (size_t)by * 128 * HID;
    const size_t bo = (size_t)bx * 128 * HID;
    mm128_core(g_hsh + ao, g_hsl + ao, g_wh + bo, g_wl + bo,
               C + (size_t)by * 128 * ldc + n0, ldc);
}

// output projection: grid (8, 8)
__global__ __launch_bounds__(256) void out_mm(float* __restrict__ out)
{
    const int bx = blockIdx.x, by = blockIdx.y;
    const size_t ao = (size_t)by * 128 * HID;
    const size_t bo = (size_t)(1536 + bx * 128) * HID;
    mm128_core(g_yh + ao, g_yl + ao, g_wh + bo, g_wl + bo,
               out + (size_t)by * 128 * HID + bx * 128, HID);
}

// ============================================================================
// phi mapping
// ============================================================================
__device__ __forceinline__ void phi_map(int D, int& pi, int& pj, float& sc)
{
    pi = 16; pj = 16; sc = 0.f;
    if (D == 0)        { sc = 1.f; }
    else if (D < 17)   { pi = D - 1;  sc = 0.5f; }
    else if (D < 33)   { pi = D - 17; pj = pi; sc = 0.17677669529663687f; }
    else if (D < DPHI) {
        int pp = D - 33, i = 0;
        while (pp >= 15 - i) { pp -= 15 - i; i++; }
        pi = i; pj = i + 1 + pp; sc = 0.25f;
    }
}

// ============================================================================
// Kernel A: per chunk, G = phiK^T @ V and colsum(phiK).
// ============================================================================
struct SmemA {
    float P[DPAD][68];
    float V[CHK][68];
    float R[CHK][17];
};

__global__ __launch_bounds__(256) void chunk_outer()
{
    extern __shared__ float sm_raw[];
    SmemA* s = (SmemA*)sm_raw;
    const int task = blockIdx.x;
    const int bh = task >> 3, c = task & 7;
    const int b = bh >> 4, h = bh & 15, t0 = c * CHK;
    const int tid = threadIdx.x;

    for (int e = tid; e < CHK * FD; e += 256) {
        int t = e >> 4, f = e & 15;
        s->R[t][f] = g_k[((size_t)(b * TT + t0 + t)) * (NH * FD) + h * FD + f];
    }
    if (tid < CHK) s->R[tid][16] = 1.f;
    for (int e = tid; e < CHK * 16; e += 256) {
        int t = e >> 4, d4 = (e & 15) << 2;
        *(float4*)&s->V[t][d4] =
            *(const float4*)&g_v[((size_t)(b * TT + t0 + t)) * HID + h * HD + d4];
    }
    __syncthreads();

    if (tid < DPAD) {
        int pi, pj; float sc;
        phi_map(tid, pi, pj, sc);
#pragma unroll 4
        for (int t = 0; t < CHK; t++)
            s->P[tid][t] = sc * s->R[t][pi] * s->R[t][pj];
    }
    __syncthreads();

    const int tx = tid & 15, ty = tid >> 4;
    float acc[10][4];
#pragma unroll
    for (int r = 0; r < 10; r++)
#pragma unroll
        for (int j = 0; j < 4; j++) acc[r][j] = 0.f;

    for (int t = 0; t < CHK; t++) {
        float4 v4 = *(float4*)&s->V[t][tx << 2];
#pragma unroll
        for (int r = 0; r < 10; r++) {
            float p = s->P[ty * 10 + r][t];
            acc[r][0] = fmaf(p, v4.x, acc[r][0]);
            acc[r][1] = fmaf(p, v4.y, acc[r][1]);
            acc[r][2] = fmaf(p, v4.z, acc[r][2]);
            acc[r][3] = fmaf(p, v4.w, acc[r][3]);
        }
    }

    float* Gp = g_G + (size_t)task * (DPAD * HD);
#pragma unroll
    for (int r = 0; r < 10; r++)
        *(float4*)&Gp[(ty * 10 + r) * HD + (tx << 2)] =
            make_float4(acc[r][0], acc[r][1], acc[r][2], acc[r][3]);

    if (tid < DPAD) {
        float cs = 0.f;
#pragma unroll 4
        for (int t = 0; t < CHK; t++) cs += s->P[tid][t];
        g_cs[(size_t)task * DPAD + tid] = cs;
    }
}

// ============================================================================
// Kernel B: exclusive prefix over chunks. grid (NBH, 8)
// ============================================================================
__global__ __launch_bounds__(256) void prefix_kernel()
{
    const int bh = blockIdx.x, z = blockIdx.y;
    const int tid = threadIdx.x;
    const size_t base = (size_t)bh * NC;
    const int e0 = z * (DPAD * HD / 8), e1 = e0 + (DPAD * HD / 8);

    for (int e = e0 + tid; e < e1; e += 256) {
        float carry = 0.f;
#pragma unroll
        for (int c = 0; c < NC; c++) {
            size_t idx = (base + c) * (DPAD * HD) + e;
            float v = g_G[idx];
            g_S[idx] = carry;
            carry += v;
        }
    }
    if (z == 0) {
        for (int e = tid; e < DPAD; e += 256) {
            float carry = 0.f;
#pragma unroll
            for (int c = 0; c < NC; c++) {
                size_t idx = (base + c) * DPAD + e;
                float v = g_cs[idx];
                g_Z[idx] = carry;
                carry += v;
            }
        }
    }
}

// ============================================================================
// Kernel C: intra-chunk attention + inter-chunk state.
// ============================================================================
struct SmemC {
    float Q[DPAD][68];
    float K[DPAD][68];
    float A[CHK][68];
    float V[CHK][68];
    float RQ[CHK][17];
    float RK[CHK][17];
    float Den[CHK];
    float Di[CHK];
};

__global__ __launch_bounds__(256) void attn_chunk()
{
    extern __shared__ float sm_raw[];
    SmemC* s = (SmemC*)sm_raw;
    const int task = blockIdx.x;
    const int bh = task >> 3, c = task & 7;
    const int b = bh >> 4, h = bh & 15, t0 = c * CHK;
    const int tid = threadIdx.x;

    for (int e = tid; e < CHK * FD; e += 256) {
        int t = e >> 4, f = e & 15;
        size_t row = (size_t)(b * TT + t0 + t);
        s->RQ[t][f] = g_q[row * (NH * FD) + h * FD + f];
        s->RK[t][f] = g_k[row * (NH * FD) + h * FD + f];
    }
    if (tid < CHK) { s->RQ[tid][16] = 1.f; s->RK[tid][16] = 1.f; }
    for (int e = tid; e < CHK * 16; e += 256) {
        int t = e >> 4, d4 = (e & 15) << 2;
        *(float4*)&s->V[t][d4] =
            *(const float4*)&g_v[((size_t)(b * TT + t0 + t)) * HID + h * HD + d4];
    }
    __syncthreads();

    if (tid < DPAD) {
        int pi, pj; float sc;
        phi_map(tid, pi, pj, sc);
#pragma unroll 4
        for (int t = 0; t < CHK; t++) {
            s->Q[tid][t] = sc * s->RQ[t][pi] * s->RQ[t][pj];
            s->K[tid][t] = sc * s->RK[t][pi] * s->RK[t][pj];
        }
    }
    __syncthreads();

    const int tx = tid & 15, ty = tid >> 4;

    float a[4][4];
#pragma unroll
    for (int i = 0; i < 4; i++)
#pragma unroll
        for (int j = 0; j < 4; j++) a[i][j] = 0.f;

#pragma unroll 4
    for (int k = 0; k < DPAD; k++) {
        float4 qa = *(float4*)&s->Q[k][ty << 2];
        float4 kb = *(float4*)&s->K[k][tx << 2];
        a[0][0] = fmaf(qa.x, kb.x, a[0][0]);
        a[0][1] = fmaf(qa.x, kb.y, a[0][1]);
        a[0][2] = fmaf(qa.x, kb.z, a[0][2]);
        a[0][3] = fmaf(qa.x, kb.w, a[0][3]);
        a[1][0] = fmaf(qa.y, kb.x, a[1][0]);
        a[1][1] = fmaf(qa.y, kb.y, a[1][1]);
        a[1][2] = fmaf(qa.y, kb.z, a[1][2]);
        a[1][3] = fmaf(qa.y, kb.w, a[1][3]);
        a[2][0] = fmaf(qa.z, kb.x, a[2][0]);
        a[2][1] = fmaf(qa.z, kb.y, a[2][1]);
        a[2][2] = fmaf(qa.z, kb.z, a[2][2]);
        a[2][3] = fmaf(qa.z, kb.w, a[2][3]);
        a[3][0] = fmaf(qa.w, kb.x, a[3][0]);
        a[3][1] = fmaf(qa.w, kb.y, a[3][1]);
        a[3][2] = fmaf(qa.w, kb.z, a[3][2]);
        a[3][3] = fmaf(qa.w, kb.w, a[3][3]);
    }

    float p[4] = {0.f, 0.f, 0.f, 0.f};
#pragma unroll
    for (int i = 0; i < 4; i++) {
        int trow = (ty << 2) + i;
        float4 m;
        m.x = ((tx << 2) + 0 <= trow) ? a[i][0] : 0.f;
        m.y = ((tx << 2) + 1 <= trow) ? a[i][1] : 0.f;
        m.z = ((tx << 2) + 2 <= trow) ? a[i][2] : 0.f;
        m.w = ((tx << 2) + 3 <= trow) ? a[i][3] : 0.f;
        *(float4*)&s->A[trow][tx << 2] = m;
        p[i] = m.x + m.y + m.z + m.w;
    }
#pragma unroll
    for (int i = 0; i < 4; i++) {
        p[i] += __shfl_xor_sync(0xffffffffu, p[i], 1);
        p[i] += __shfl_xor_sync(0xffffffffu, p[i], 2);
        p[i] += __shfl_xor_sync(0xffffffffu, p[i], 4);
        p[i] += __shfl_xor_sync(0xffffffffu, p[i], 8);
    }
    if (tx == 0) {
#pragma unroll
        for (int i = 0; i < 4; i++) s->Den[(ty << 2) + i] = p[i];
    }

    if (tid < CHK) {
        const float* Zp = g_Z + (size_t)task * DPAD;
        float di = 0.f;
#pragma unroll 4
        for (int k = 0; k < DPAD; k++)
            di = fmaf(s->Q[k][tid], __ldg(&Zp[k]), di);
        s->Di[tid] = di;
    }
    __syncthreads();

    float y[4][4];
#pragma unroll
    for (int i = 0; i < 4; i++)
#pragma unroll
        for (int j = 0; j < 4; j++) y[i][j] = 0.f;

#pragma unroll 4
    for (int k = 0; k < CHK; k++) {
        float4 v4 = *(float4*)&s->V[k][tx << 2];
        float a0 = s->A[(ty << 2) + 0][k];
        float a1 = s->A[(ty << 2) + 1][k];
        float a2 = s->A[(ty << 2) + 2][k];
        float a3 = s->A[(ty << 2) + 3][k];
        y[0][0] = fmaf(a0, v4.x, y[0][0]); y[0][1] = fmaf(a0, v4.y, y[0][1]);
        y[0][2] = fmaf(a0, v4.z, y[0][2]); y[0][3] = fmaf(a0, v4.w, y[0][3]);
        y[1][0] = fmaf(a1, v4.x, y[1][0]); y[1][1] = fmaf(a1, v4.y, y[1][1]);
        y[1][2] = fmaf(a1, v4.z, y[1][2]); y[1][3] = fmaf(a1, v4.w, y[1][3]);
        y[2][0] = fmaf(a2, v4.x, y[2][0]); y[2][1] = fmaf(a2, v4.y, y[2][1]);
        y[2][2] = fmaf(a2, v4.z, y[2][2]); y[2][3] = fmaf(a2, v4.w, y[2][3]);
        y[3][0] = fmaf(a3, v4.x, y[3][0]); y[3][1] = fmaf(a3, v4.y, y[3][1]);
        y[3][2] = fmaf(a3, v4.z, y[3][2]); y[3][3] = fmaf(a3, v4.w, y[3][3]);
    }

    const float* Sp = g_S + (size_t)task * (DPAD * HD);
#pragma unroll 4
    for (int k = 0; k < DPAD; k++) {
        float4 s4 = __ldg((const float4*)&Sp[k * HD + (tx << 2)]);
        float4 q4 = *(float4*)&s->Q[k][ty << 2];
        y[0][0] = fmaf(q4.x, s4.x, y[0][0]); y[0][1] = fmaf(q4.x, s4.y, y[0][1]);
        y[0][2] = fmaf(q4.x, s4.z, y[0][2]); y[0][3] = fmaf(q4.x, s4.w, y[0][3]);
        y[1][0] = fmaf(q4.y, s4.x, y[1][0]); y[1][1] = fmaf(q4.y, s4.y, y[1][1]);
        y[1][2] = fmaf(q4.y, s4.z, y[1][2]); y[1][3] = fmaf(q4.y, s4.w, y[1][3]);
        y[2][0] = fmaf(q4.z, s4.x, y[2][0]); y[2][1] = fmaf(q4.z, s4.y, y[2][1]);
        y[2][2] = fmaf(q4.z, s4.z, y[2][2]); y[2][3] = fmaf(q4.z, s4.w, y[2][3]);
        y[3][0] = fmaf(q4.w, s4.x, y[3][0]); y[3][1] = fmaf(q4.w, s4.y, y[3][1]);
        y[3][2] = fmaf(q4.w, s4.z, y[3][2]); y[3][3] = fmaf(q4.w, s4.w, y[3][3]);
    }

#pragma unroll
    for (int i = 0; i < 4; i++) {
        int trow = (ty << 2) + i;
        float dn = 1.f / (s->Den[trow] + s->Di[trow] + EPSI);
        float4 o = make_float4(y[i][0] * dn, y[i][1] * dn, y[i][2] * dn, y[i][3] * dn);
        *(float4*)&g_y[((size_t)(b * TT + t0 + trow)) * HID + h * HD + (tx << 2)] = o;
    }
}

// ============================================================================
// kernel_launch
// ============================================================================
extern "C" void kernel_launch(void* const* d_in, const int* in_sizes, int n_in,
                              void* d_out, int out_size)
{
    const float* hs = (const float*)d_in[0];
    const float* Wq = (const float*)d_in[1];
    const float* Wk = (const float*)d_in[2];
    const float* Wv = (const float*)d_in[3];
    const float* Wo = (const float*)d_in[4];
    float* out = (float*)d_out;

    __nv_bfloat16 *bhsh, *bhsl, *byh, *byl;
    cudaGetSymbolAddress((void**)&bhsh, g_hsh);
    cudaGetSymbolAddress((void**)&bhsl, g_hsl);
    cudaGetSymbolAddress((void**)&byh, g_yh);
    cudaGetSymbolAddress((void**)&byl, g_yl);
    float* py;
    cudaGetSymbolAddress((void**)&py, g_y);

    const int smemA = (int)sizeof(SmemA);
    const int smemC = (int)sizeof(SmemC);
    cudaFuncSetAttribute(chunk_outer, cudaFuncAttributeMaxDynamicSharedMemorySize, smemA);
    cudaFuncSetAttribute(attn_chunk,  cudaFuncAttributeMaxDynamicSharedMemorySize, smemC);

    // bf16 hi/lo conversions
    conv_w<<<WROWS, 256>>>(Wq, Wk, Wv, Wo);
    conv_x<<<BT * HID / 1024, 256>>>(hs, bhsh, bhsl);

    // q/k/v projections on tensor cores (mma.sync)
    proj_mm<<<dim3(12, 8), 256>>>();

    // chunked causal linear attention (scalar, proven)
    chunk_outer<<<NTASK, 256, smemA>>>();
    prefix_kernel<<<dim3(NBH, 8), 256>>>();
    attn_chunk<<<NTASK, 256, smemC>>>();

    // output projection on tensor cores
    conv_x<<<BT * HID / 1024, 256>>>(py, byh, byl);
    out_mm<<<dim3(8, 8), 256>>>(out);
}

// round 15
// speedup vs baseline: 2.1631x; 1.0389x over previous
#include <cuda_runtime.h>
#include <cuda_bf16.h>
#include <cstdint>
#include <cstddef>

#define BB   2
#define TT   512
#define BT   1024
#define NH   16
#define FD   16
#define HD   64
#define HID  1024
#define DPHI 153
#define DPAD 160
#define CHK  64
#define NC   8
#define NBH  32
#define NTASK (NBH*NC)
#define EPSI 1e-12f

// ---- scratch ----
__device__ float g_q[BT * NH * FD];
__device__ float g_k[BT * NH * FD];
__device__ float g_v[BT * HID];
__device__ float g_G[NTASK * DPAD * HD];
__device__ float g_cs[NTASK * DPAD];
__device__ float g_Z[NTASK * DPAD];
__device__ __nv_bfloat16 g_Sh[NTASK * DPAD * HD];   // exclusive prefix of G, hi
__device__ __nv_bfloat16 g_Sl[NTASK * DPAD * HD];   // lo

// bf16 split buffers
__device__ __nv_bfloat16 g_hsh[BT * HID];
__device__ __nv_bfloat16 g_hsl[BT * HID];
__device__ __nv_bfloat16 g_yh[BT * HID];
__device__ __nv_bfloat16 g_yl[BT * HID];
#define WROWS 2560
__device__ __nv_bfloat16 g_wh[WROWS * HID];
__device__ __nv_bfloat16 g_wl[WROWS * HID];

__device__ __forceinline__ uint32_t s2u(const void* p) {
    uint32_t a;
    asm("{ .reg .u64 t; cvta.to.shared.u64 t, %1; cvt.u32.u64 %0, t; }"
        : "=r"(a) : "l"(p));
    return a;
}
__device__ __forceinline__ void ldm4(uint32_t& r0, uint32_t& r1,
                                     uint32_t& r2, uint32_t& r3, uint32_t a) {
    asm volatile("ldmatrix.sync.aligned.m8n8.x4.shared.b16 {%0,%1,%2,%3}, [%4];"
                 : "=r"(r0), "=r"(r1), "=r"(r2), "=r"(r3) : "r"(a));
}
__device__ __forceinline__ void ldm4t(uint32_t& r0, uint32_t& r1,
                                      uint32_t& r2, uint32_t& r3, uint32_t a) {
    asm volatile("ldmatrix.sync.aligned.m8n8.x4.trans.shared.b16 {%0,%1,%2,%3}, [%4];"
                 : "=r"(r0), "=r"(r1), "=r"(r2), "=r"(r3) : "r"(a));
}
__device__ __forceinline__ void mma16816(float* c, const uint32_t* a,
                                         const uint32_t* b) {
    asm volatile(
        "mma.sync.aligned.m16n8k16.row.col.f32.bf16.bf16.f32 "
        "{%0,%1,%2,%3}, {%4,%5,%6,%7}, {%8,%9}, {%0,%1,%2,%3};"
        : "+f"(c[0]), "+f"(c[1]), "+f"(c[2]), "+f"(c[3])
        : "r"(a[0]), "r"(a[1]), "r"(a[2]), "r"(a[3]), "r"(b[0]), "r"(b[1]));
}
__device__ __forceinline__ void bsplit(float v, __nv_bfloat16& h, __nv_bfloat16& l) {
    h = __float2bfloat16(v);
    l = __float2bfloat16(v - __bfloat162float(h));
}

// ============================================================================
// bf16-split conversion kernels
// ============================================================================
__global__ __launch_bounds__(256) void conv_x(
    const float* __restrict__ src, __nv_bfloat16* __restrict__ dh,
    __nv_bfloat16* __restrict__ dl)
{
    size_t base = (size_t)blockIdx.x * 1024 + threadIdx.x * 4;
    float4 x = *(const float4*)(src + base);
    __nv_bfloat16 h0, l0, h1, l1, h2, l2, h3, l3;
    bsplit(x.x, h0, l0); bsplit(x.y, h1, l1);
    bsplit(x.z, h2, l2); bsplit(x.w, h3, l3);
    __nv_bfloat162* H = (__nv_bfloat162*)(dh + base);
    __nv_bfloat162* L = (__nv_bfloat162*)(dl + base);
    H[0] = __nv_bfloat162(h0, h1); H[1] = __nv_bfloat162(h2, h3);
    L[0] = __nv_bfloat162(l0, l1); L[1] = __nv_bfloat162(l2, l3);
}

__global__ __launch_bounds__(256) void conv_w(
    const float* __restrict__ Wq, const float* __restrict__ Wk,
    const float* __restrict__ Wv, const float* __restrict__ Wo)
{
    const int r = blockIdx.x;
    const float* src;
    if (r < 256)       src = Wq + (size_t)r * HID;
    else if (r < 512)  src = Wk + (size_t)(r - 256) * HID;
    else if (r < 1536) src = Wv + (size_t)(r - 512) * HID;
    else               src = Wo + (size_t)(r - 1536) * HID;
    size_t base = (size_t)r * HID + threadIdx.x * 4;
    float4 x = *(const float4*)(src + threadIdx.x * 4);
    __nv_bfloat16 h0, l0, h1, l1, h2, l2, h3, l3;
    bsplit(x.x, h0, l0); bsplit(x.y, h1, l1);
    bsplit(x.z, h2, l2); bsplit(x.w, h3, l3);
    __nv_bfloat162* H = (__nv_bfloat162*)(g_wh + base);
    __nv_bfloat162* L = (__nv_bfloat162*)(g_wl + base);
    H[0] = __nv_bfloat162(h0, h1); H[1] = __nv_bfloat162(h2, h3);
    L[0] = __nv_bfloat162(l0, l1); L[1] = __nv_bfloat162(l2, l3);
}

// ============================================================================
// mma.sync bf16-split GEMM (verified r12): C[128,128] = A[128,1024]@B[128,1024]^T
// ============================================================================
#define SROW 40

__device__ void mm128_core(
    const __nv_bfloat16* __restrict__ Ah, const __nv_bfloat16* __restrict__ Al,
    const __nv_bfloat16* __restrict__ Bh, const __nv_bfloat16* __restrict__ Bl,
    float* __restrict__ C, int ldc)
{
    __shared__ __align__(16) __nv_bfloat16 sAh[128 * SROW];
    __shared__ __align__(16) __nv_bfloat16 sAl[128 * SROW];
    __shared__ __align__(16) __nv_bfloat16 sBh[128 * SROW];
    __shared__ __align__(16) __nv_bfloat16 sBl[128 * SROW];

    const int tid = threadIdx.x;
    const int wid = tid >> 5, lane = tid & 31;
    const int warpM = (wid >> 2) * 64;
    const int warpN = (wid & 3) * 32;

    const int lt = lane >> 3, lr = lane & 7;
    const int aRow = lr + (lt & 1) * 8;
    const int aByte = (lt >> 1) * 16;
    const int bRow = lr + (lt >> 1) * 8;
    const int bByte = (lt & 1) * 16;

    const uint32_t uAh = s2u(sAh), uAl = s2u(sAl);
    const uint32_t uBh = s2u(sBh), uBl = s2u(sBl);

    const int r0c = tid >> 2, q0 = (tid & 3) * 8;
    const int r1c = (tid + 256) >> 2, q1 = ((tid + 256) & 3) * 8;

    float acc[4][4][4];
#pragma unroll
    for (int i = 0; i < 4; i++)
#pragma unroll
        for (int j = 0; j < 4; j++)
#pragma unroll
            for (int e = 0; e < 4; e++) acc[i][j][e] = 0.f;

    for (int kc = 0; kc < HID / 32; kc++) {
        const int kb = kc * 32;
        {
            uint4 vA0 = *(const uint4*)(Ah + (size_t)r0c * HID + kb + q0);
            uint4 vA1 = *(const uint4*)(Ah + (size_t)r1c * HID + kb + q1);
            uint4 wA0 = *(const uint4*)(Al + (size_t)r0c * HID + kb + q0);
            uint4 wA1 = *(const uint4*)(Al + (size_t)r1c * HID + kb + q1);
            uint4 vB0 = *(const uint4*)(Bh + (size_t)r0c * HID + kb + q0);
            uint4 vB1 = *(const uint4*)(Bh + (size_t)r1c * HID + kb + q1);
            uint4 wB0 = *(const uint4*)(Bl + (size_t)r0c * HID + kb + q0);
            uint4 wB1 = *(const uint4*)(Bl + (size_t)r1c * HID + kb + q1);
            __syncthreads();
            *(uint4*)(sAh + r0c * SROW + q0) = vA0;
            *(uint4*)(sAh + r1c * SROW + q1) = vA1;
            *(uint4*)(sAl + r0c * SROW + q0) = wA0;
            *(uint4*)(sAl + r1c * SROW + q1) = wA1;
            *(uint4*)(sBh + r0c * SROW + q0) = vB0;
            *(uint4*)(sBh + r1c * SROW + q1) = vB1;
            *(uint4*)(sBl + r0c * SROW + q0) = wB0;
            *(uint4*)(sBl + r1c * SROW + q1) = wB1;
        }
        __syncthreads();

#pragma unroll
        for (int s = 0; s < 2; s++) {
            const int sb = s * 32;
            uint32_t ah[4][4], bh[4][2], bl[4][2], al[4][4];

#pragma unroll
            for (int mi = 0; mi < 4; mi++)
                ldm4(ah[mi][0], ah[mi][1], ah[mi][2], ah[mi][3],
                     uAh + (warpM + mi * 16 + aRow) * 80 + sb + aByte);
#pragma unroll
            for (int g = 0; g < 2; g++)
                ldm4(bh[2 * g][0], bh[2 * g][1], bh[2 * g + 1][0], bh[2 * g + 1][1],
                     uBh + (warpN + g * 16 + bRow) * 80 + sb + bByte);
#pragma unroll
            for (int mi = 0; mi < 4; mi++)
#pragma unroll
                for (int ng = 0; ng < 4; ng++)
                    mma16816(acc[mi][ng], ah[mi], bh[ng]);

#pragma unroll
            for (int g = 0; g < 2; g++)
                ldm4(bl[2 * g][0], bl[2 * g][1], bl[2 * g + 1][0], bl[2 * g + 1][1],
                     uBl + (warpN + g * 16 + bRow) * 80 + sb + bByte);
#pragma unroll
            for (int mi = 0; mi < 4; mi++)
#pragma unroll
                for (int ng = 0; ng < 4; ng++)
                    mma16816(acc[mi][ng], ah[mi], bl[ng]);

#pragma unroll
            for (int mi = 0; mi < 4; mi++)
                ldm4(al[mi][0], al[mi][1], al[mi][2], al[mi][3],
                     uAl + (warpM + mi * 16 + aRow) * 80 + sb + aByte);
#pragma unroll
            for (int mi = 0; mi < 4; mi++)
#pragma unroll
                for (int ng = 0; ng < 4; ng++)
                    mma16816(acc[mi][ng], al[mi], bh[ng]);
        }
    }

    const int cr = lane >> 2, cc = (lane & 3) * 2;
#pragma unroll
    for (int mi = 0; mi < 4; mi++) {
#pragma unroll
        for (int ng = 0; ng < 4; ng++) {
            float* cp0 = C + (size_t)(warpM + mi * 16 + cr) * ldc
                           + warpN + ng * 8 + cc;
            float* cp1 = cp0 + 8 * ldc;
            cp0[0] = acc[mi][ng][0]; cp0[1] = acc[mi][ng][1];
            cp1[0] = acc[mi][ng][2]; cp1[1] = acc[mi][ng][3];
        }
    }
}

__global__ __launch_bounds__(256) void proj_mm()
{
    const int bx = blockIdx.x, by = blockIdx.y;
    float* C; int ldc, n0;
    if (bx < 2)      { C = g_q; ldc = NH * FD; n0 = bx * 128; }
    else if (bx < 4) { C = g_k; ldc = NH * FD; n0 = (bx - 2) * 128; }
    else             { C = g_v; ldc = HID;     n0 = (bx - 4) * 128; }
    const size_t ao = (size_t)by * 128 * HID;
    const size_t bo = (size_t)bx * 128 * HID;
    mm128_core(g_hsh + ao, g_hsl + ao, g_wh + bo, g_wl + bo,
               C + (size_t)by * 128 * ldc + n0, ldc);
}

__global__ __launch_bounds__(256) void out_mm(float* __restrict__ out)
{
    const int bx = blockIdx.x, by = blockIdx.y;
    const size_t ao = (size_t)by * 128 * HID;
    const size_t bo = (size_t)(1536 + bx * 128) * HID;
    mm128_core(g_yh + ao, g_yl + ao, g_wh + bo, g_wl + bo,
               out + (size_t)by * 128 * HID + bx * 128, HID);
}

// ============================================================================
// phi mapping
// ============================================================================
__device__ __forceinline__ void phi_map(int D, int& pi, int& pj, float& sc)
{
    pi = 16; pj = 16; sc = 0.f;
    if (D == 0)        { sc = 1.f; }
    else if (D < 17)   { pi = D - 1;  sc = 0.5f; }
    else if (D < 33)   { pi = D - 17; pj = pi; sc = 0.17677669529663687f; }
    else if (D < DPHI) {
        int pp = D - 33, i = 0;
        while (pp >= 15 - i) { pp -= 15 - i; i++; }
        pi = i; pj = i + 1 + pp; sc = 0.25f;
    }
}

// ============================================================================
// Kernel A: per chunk, G = phiK^T @ V and colsum(phiK). (scalar, proven)
// ============================================================================
struct SmemA {
    float P[DPAD][68];
    float V[CHK][68];
    float R[CHK][17];
};

__global__ __launch_bounds__(256) void chunk_outer()
{
    extern __shared__ float sm_raw[];
    SmemA* s = (SmemA*)sm_raw;
    const int task = blockIdx.x;
    const int bh = task >> 3, c = task & 7;
    const int b = bh >> 4, h = bh & 15, t0 = c * CHK;
    const int tid = threadIdx.x;

    for (int e = tid; e < CHK * FD; e += 256) {
        int t = e >> 4, f = e & 15;
        s->R[t][f] = g_k[((size_t)(b * TT + t0 + t)) * (NH * FD) + h * FD + f];
    }
    if (tid < CHK) s->R[tid][16] = 1.f;
    for (int e = tid; e < CHK * 16; e += 256) {
        int t = e >> 4, d4 = (e & 15) << 2;
        *(float4*)&s->V[t][d4] =
            *(const float4*)&g_v[((size_t)(b * TT + t0 + t)) * HID + h * HD + d4];
    }
    __syncthreads();

    if (tid < DPAD) {
        int pi, pj; float sc;
        phi_map(tid, pi, pj, sc);
#pragma unroll 4
        for (int t = 0; t < CHK; t++)
            s->P[tid][t] = sc * s->R[t][pi] * s->R[t][pj];
    }
    __syncthreads();

    const int tx = tid & 15, ty = tid >> 4;
    float acc[10][4];
#pragma unroll
    for (int r = 0; r < 10; r++)
#pragma unroll
        for (int j = 0; j < 4; j++) acc[r][j] = 0.f;

    for (int t = 0; t < CHK; t++) {
        float4 v4 = *(float4*)&s->V[t][tx << 2];
#pragma unroll
        for (int r = 0; r < 10; r++) {
            float p = s->P[ty * 10 + r][t];
            acc[r][0] = fmaf(p, v4.x, acc[r][0]);
            acc[r][1] = fmaf(p, v4.y, acc[r][1]);
            acc[r][2] = fmaf(p, v4.z, acc[r][2]);
            acc[r][3] = fmaf(p, v4.w, acc[r][3]);
        }
    }

    float* Gp = g_G + (size_t)task * (DPAD * HD);
#pragma unroll
    for (int r = 0; r < 10; r++)
        *(float4*)&Gp[(ty * 10 + r) * HD + (tx << 2)] =
            make_float4(acc[r][0], acc[r][1], acc[r][2], acc[r][3]);

    if (tid < DPAD) {
        float cs = 0.f;
#pragma unroll 4
        for (int t = 0; t < CHK; t++) cs += s->P[tid][t];
        g_cs[(size_t)task * DPAD + tid] = cs;
    }
}

// ============================================================================
// Kernel B: exclusive prefix over chunks -> bf16 hi/lo S. grid (NBH, 8)
// ============================================================================
__global__ __launch_bounds__(256) void prefix_kernel()
{
    const int bh = blockIdx.x, z = blockIdx.y;
    const int tid = threadIdx.x;
    const size_t base = (size_t)bh * NC;
    const int e0 = z * (DPAD * HD / 8), e1 = e0 + (DPAD * HD / 8);

    for (int e = e0 + tid; e < e1; e += 256) {
        float carry = 0.f;
#pragma unroll
        for (int c = 0; c < NC; c++) {
            size_t idx = (base + c) * (DPAD * HD) + e;
            __nv_bfloat16 hh, ll;
            bsplit(carry, hh, ll);
            g_Sh[idx] = hh;
            g_Sl[idx] = ll;
            carry += g_G[idx];
        }
    }
    if (z == 0) {
        for (int e = tid; e < DPAD; e += 256) {
            float carry = 0.f;
#pragma unroll
            for (int c = 0; c < NC; c++) {
                size_t idx = (base + c) * DPAD + e;
                float v = g_cs[idx];
                g_Z[idx] = carry;
                carry += v;
            }
        }
    }
}

// ============================================================================
// Kernel C v2: tensor-core intra-chunk attention.
//   phase1: A = phiQ @ phiK^T (bf16 split, 3 products), mask, store bf16 split
//   phase2: y = Am @ V + phiQ @ S (bf16 split), normalize, write yh/yl
// 256 threads, warp tile 32x16, smem = 178176 B.
// ============================================================================
#define QROW 168   // bf16 per phiQ/phiK row (160 + 4 pad -> 336 B)
#define VROW 72    // bf16 per V/A/S row (64 + 8 pad -> 144 B)
#define ATT_RQ   0
#define ATT_RK   4352
#define ATT_DEN  8704
#define ATT_QH   9216
#define ATT_QL   30720
#define ATT_KH   52224
#define ATT_KL   73728
#define ATT_VH   95232
#define ATT_VL   104448
#define ATT_AH   113664
#define ATT_AL   122880
#define ATT_SH   132096
#define ATT_SL   155136
#define ATT_SMEM 178176

__global__ __launch_bounds__(256) void attn_chunk()
{
    extern __shared__ char sm[];
    float* RQ  = (float*)(sm + ATT_RQ);    // [64][17]
    float* RK  = (float*)(sm + ATT_RK);
    float* Den = (float*)(sm + ATT_DEN);   // [64]
    __nv_bfloat16* Qh = (__nv_bfloat16*)(sm + ATT_QH);  // [64][QROW]
    __nv_bfloat16* Ql = (__nv_bfloat16*)(sm + ATT_QL);
    __nv_bfloat16* Kh = (__nv_bfloat16*)(sm + ATT_KH);
    __nv_bfloat16* Kl = (__nv_bfloat16*)(sm + ATT_KL);
    __nv_bfloat16* Vh = (__nv_bfloat16*)(sm + ATT_VH);  // [64][VROW]
    __nv_bfloat16* Vl = (__nv_bfloat16*)(sm + ATT_VL);
    __nv_bfloat16* Ah = (__nv_bfloat16*)(sm + ATT_AH);  // [64][VROW]
    __nv_bfloat16* Al = (__nv_bfloat16*)(sm + ATT_AL);
    __nv_bfloat16* Sh = (__nv_bfloat16*)(sm + ATT_SH);  // [160][VROW]
    __nv_bfloat16* Sl = (__nv_bfloat16*)(sm + ATT_SL);

    const int task = blockIdx.x;
    const int bh = task >> 3, c = task & 7;
    const int b = bh >> 4, h = bh & 15, t0 = c * CHK;
    const int tid = threadIdx.x;
    const int wid = tid >> 5, lane = tid & 31;
    const int warpM = (wid >> 2) * 32;        // 0 or 32
    const int warpN = (wid & 3) * 16;         // 0,16,32,48
    const int lt = lane >> 3, lr = lane & 7;
    const int aRow = lr + (lt & 1) * 8;       // also trans-B row pattern
    const int aByte = (lt >> 1) * 16;         // also trans-B byte pattern
    const int bRow = lr + (lt >> 1) * 8;
    const int bByte = (lt & 1) * 16;

    const uint32_t uQh = s2u(Qh), uQl = s2u(Ql);
    const uint32_t uKh = s2u(Kh), uKl = s2u(Kl);
    const uint32_t uVh = s2u(Vh), uVl = s2u(Vl);
    const uint32_t uAh = s2u(Ah), uAl = s2u(Al);
    const uint32_t uSh = s2u(Sh), uSl = s2u(Sl);

    // ---- stage loads ----
    for (int e = tid; e < CHK * FD; e += 256) {
        int t = e >> 4, f = e & 15;
        size_t row = (size_t)(b * TT + t0 + t);
        RQ[t * 17 + f] = g_q[row * (NH * FD) + h * FD + f];
        RK[t * 17 + f] = g_k[row * (NH * FD) + h * FD + f];
    }
    if (tid < CHK) { RQ[tid * 17 + 16] = 1.f; RK[tid * 17 + 16] = 1.f; }

    // V fp32 -> bf16 split into [t][d] rows
    for (int e = tid; e < CHK * 16; e += 256) {
        int t = e >> 4, d0 = (e & 15) << 2;
        float4 v = *(const float4*)&g_v[((size_t)(b * TT + t0 + t)) * HID + h * HD + d0];
        __nv_bfloat16 hh, ll;
        bsplit(v.x, hh, ll); Vh[t * VROW + d0 + 0] = hh; Vl[t * VROW + d0 + 0] = ll;
        bsplit(v.y, hh, ll); Vh[t * VROW + d0 + 1] = hh; Vl[t * VROW + d0 + 1] = ll;
        bsplit(v.z, hh, ll); Vh[t * VROW + d0 + 2] = hh; Vl[t * VROW + d0 + 2] = ll;
        bsplit(v.w, hh, ll); Vh[t * VROW + d0 + 3] = hh; Vl[t * VROW + d0 + 3] = ll;
    }

    // S split loads: 1280 16B chunks per array
    {
        const size_t sbase = (size_t)task * (DPAD * HD);
        for (int cc2 = tid; cc2 < 1280; cc2 += 256) {
            int rowD = cc2 >> 3, off = (cc2 & 7) * 8;
            *(uint4*)(Sh + rowD * VROW + off) =
                *(const uint4*)(g_Sh + sbase + rowD * HD + off);
            *(uint4*)(Sl + rowD * VROW + off) =
                *(const uint4*)(g_Sl + sbase + rowD * HD + off);
        }
    }
    __syncthreads();

    // ---- feature map -> bf16 split, [t][D] rows ----
    {
        const int t = tid & 63, g = tid >> 6;  // 4 groups x 40 D
        const float* rq = RQ + t * 17;
        const float* rk = RK + t * 17;
        for (int D = g * 40; D < g * 40 + 40; D++) {
            int pi, pj; float sc;
            phi_map(D, pi, pj, sc);
            float vq = sc * rq[pi] * rq[pj];
            float vk = sc * rk[pi] * rk[pj];
            __nv_bfloat16 hh, ll;
            bsplit(vq, hh, ll); Qh[t * QROW + D] = hh; Ql[t * QROW + D] = ll;
            bsplit(vk, hh, ll); Kh[t * QROW + D] = hh; Kl[t * QROW + D] = ll;
        }
    }
    __syncthreads();

    // ---- phase 1: A = phiQ @ phiK^T ----
    float acc[2][2][4];
#pragma unroll
    for (int i = 0; i < 2; i++)
#pragma unroll
        for (int j = 0; j < 2; j++)
#pragma unroll
            for (int e = 0; e < 4; e++) acc[i][j][e] = 0.f;

#pragma unroll
    for (int ks = 0; ks < 10; ks++) {
        const int kb = ks * 32;  // byte offset = ks*16 elems *2
        uint32_t qh[2][4], ql[2][4], kh[2][2], kl[2][2];
#pragma unroll
        for (int mi = 0; mi < 2; mi++) {
            ldm4(qh[mi][0], qh[mi][1], qh[mi][2], qh[mi][3],
                 uQh + (warpM + mi * 16 + aRow) * 336 + kb + aByte);
            ldm4(ql[mi][0], ql[mi][1], ql[mi][2], ql[mi][3],
                 uQl + (warpM + mi * 16 + aRow) * 336 + kb + aByte);
        }
        ldm4(kh[0][0], kh[0][1], kh[1][0], kh[1][1],
             uKh + (warpN + bRow) * 336 + kb + bByte);
        ldm4(kl[0][0], kl[0][1], kl[1][0], kl[1][1],
             uKl + (warpN + bRow) * 336 + kb + bByte);
#pragma unroll
        for (int mi = 0; mi < 2; mi++)
#pragma unroll
            for (int ng = 0; ng < 2; ng++) {
                mma16816(acc[mi][ng], qh[mi], kh[ng]);
                mma16816(acc[mi][ng], qh[mi], kl[ng]);
                mma16816(acc[mi][ng], ql[mi], kh[ng]);
            }
    }

    // ---- mask + store A (bf16 split) ----
    const int cr = lane >> 2, cc = (lane & 3) * 2;
#pragma unroll
    for (int mi = 0; mi < 2; mi++) {
#pragma unroll
        for (int ng = 0; ng < 2; ng++) {
            int r0 = warpM + mi * 16 + cr;
            int c0 = warpN + ng * 8 + cc;
            float m0 = (c0     <= r0) ? acc[mi][ng][0] : 0.f;
            float m1 = (c0 + 1 <= r0) ? acc[mi][ng][1] : 0.f;
            int r1 = r0 + 8;
            float m2 = (c0     <= r1) ? acc[mi][ng][2] : 0.f;
            float m3 = (c0 + 1 <= r1) ? acc[mi][ng][3] : 0.f;
            __nv_bfloat16 h0, l0, h1, l1;
            bsplit(m0, h0, l0); bsplit(m1, h1, l1);
            *(__nv_bfloat162*)&Ah[r0 * VROW + c0] = __nv_bfloat162(h0, h1);
            *(__nv_bfloat162*)&Al[r0 * VROW + c0] = __nv_bfloat162(l0, l1);
            bsplit(m2, h0, l0); bsplit(m3, h1, l1);
            *(__nv_bfloat162*)&Ah[r1 * VROW + c0] = __nv_bfloat162(h0, h1);
            *(__nv_bfloat162*)&Al[r1 * VROW + c0] = __nv_bfloat162(l0, l1);
        }
    }
    __syncthreads();

    // ---- denominator: rowsum(Am) + phiQ . Z ----
    if (tid < CHK) {
        float den = EPSI;
        for (int j = 0; j < CHK; j++)
            den += __bfloat162float(Ah[tid * VROW + j]) +
                   __bfloat162float(Al[tid * VROW + j]);
        const float* Zp = g_Z + (size_t)task * DPAD;
        for (int D = 0; D < DPAD; D++) {
            float qv = __bfloat162float(Qh[tid * QROW + D]) +
                       __bfloat162float(Ql[tid * QROW + D]);
            den = fmaf(qv, __ldg(&Zp[D]), den);
        }
        Den[tid] = den;
    }

    // ---- phase 2: y = Am @ V + phiQ @ S ----
#pragma unroll
    for (int i = 0; i < 2; i++)
#pragma unroll
        for (int j = 0; j < 2; j++)
#pragma unroll
            for (int e = 0; e < 4; e++) acc[i][j][e] = 0.f;

#pragma unroll
    for (int ks = 0; ks < 4; ks++) {
        const int kr = ks * 16;
        uint32_t ah2[2][4], al2[2][4], bh2[2][2], bl2[2][2];
#pragma unroll
        for (int mi = 0; mi < 2; mi++) {
            ldm4(ah2[mi][0], ah2[mi][1], ah2[mi][2], ah2[mi][3],
                 uAh + (warpM + mi * 16 + aRow) * 144 + kr * 2 + aByte);
            ldm4(al2[mi][0], al2[mi][1], al2[mi][2], al2[mi][3],
                 uAl + (warpM + mi * 16 + aRow) * 144 + kr * 2 + aByte);
        }
        // trans loads: rows = k (t'), byte = n*2
        ldm4t(bh2[0][0], bh2[0][1], bh2[1][0], bh2[1][1],
              uVh + (kr + aRow) * 144 + warpN * 2 + aByte);
        ldm4t(bl2[0][0], bl2[0][1], bl2[1][0], bl2[1][1],
              uVl + (kr + aRow) * 144 + warpN * 2 + aByte);
#pragma unroll
        for (int mi = 0; mi < 2; mi++)
#pragma unroll
            for (int ng = 0; ng < 2; ng++) {
                mma16816(acc[mi][ng], ah2[mi], bh2[ng]);
                mma16816(acc[mi][ng], ah2[mi], bl2[ng]);
                mma16816(acc[mi][ng], al2[mi], bh2[ng]);
            }
    }

#pragma unroll
    for (int ks = 0; ks < 10; ks++) {
        const int kb = ks * 32;    // byte offset into Q rows
        const int kr = ks * 16;    // row offset into S
        uint32_t qh[2][4], ql[2][4], bh2[2][2], bl2[2][2];
#pragma unroll
        for (int mi = 0; mi < 2; mi++) {
            ldm4(qh[mi][0], qh[mi][1], qh[mi][2], qh[mi][3],
                 uQh + (warpM + mi * 16 + aRow) * 336 + kb + aByte);
            ldm4(ql[mi][0], ql[mi][1], ql[mi][2], ql[mi][3],
                 uQl + (warpM + mi * 16 + aRow) * 336 + kb + aByte);
        }
        ldm4t(bh2[0][0], bh2[0][1], bh2[1][0], bh2[1][1],
              uSh + (kr + aRow) * 144 + warpN * 2 + aByte);
        ldm4t(bl2[0][0], bl2[0][1], bl2[1][0], bl2[1][1],
              uSl + (kr + aRow) * 144 + warpN * 2 + aByte);
#pragma unroll
        for (int mi = 0; mi < 2; mi++)
#pragma unroll
            for (int ng = 0; ng < 2; ng++) {
                mma16816(acc[mi][ng], qh[mi], bh2[ng]);
                mma16816(acc[mi][ng], qh[mi], bl2[ng]);
                mma16816(acc[mi][ng], ql[mi], bh2[ng]);
            }
    }
    __syncthreads();   // Den ready

    // ---- normalize + write yh/yl ----
#pragma unroll
    for (int mi = 0; mi < 2; mi++) {
#pragma unroll
        for (int ng = 0; ng < 2; ng++) {
            int r0 = warpM + mi * 16 + cr;
            int c0 = warpN + ng * 8 + cc;
            int r1 = r0 + 8;
            float dn0 = 1.f / Den[r0];
            float dn1 = 1.f / Den[r1];
            float y0 = acc[mi][ng][0] * dn0, y1 = acc[mi][ng][1] * dn0;
            float y2 = acc[mi][ng][2] * dn1, y3 = acc[mi][ng][3] * dn1;
            size_t g0 = ((size_t)(b * TT + t0 + r0)) * HID + h * HD + c0;
            size_t g1 = ((size_t)(b * TT + t0 + r1)) * HID + h * HD + c0;
            __nv_bfloat16 h0, l0, h1, l1;
            bsplit(y0, h0, l0); bsplit(y1, h1, l1);
            *(__nv_bfloat162*)&g_yh[g0] = __nv_bfloat162(h0, h1);
            *(__nv_bfloat162*)&g_yl[g0] = __nv_bfloat162(l0, l1);
            bsplit(y2, h0, l0); bsplit(y3, h1, l1);
            *(__nv_bfloat162*)&g_yh[g1] = __nv_bfloat162(h0, h1);
            *(__nv_bfloat162*)&g_yl[g1] = __nv_bfloat162(l0, l1);
        }
    }
}

// ============================================================================
// kernel_launch
// ============================================================================
extern "C" void kernel_launch(void* const* d_in, const int* in_sizes, int n_in,
                              void* d_out, int out_size)
{
    const float* hs = (const float*)d_in[0];
    const float* Wq = (const float*)d_in[1];
    const float* Wk = (const float*)d_in[2];
    const float* Wv = (const float*)d_in[3];
    const float* Wo = (const float*)d_in[4];
    float* out = (float*)d_out;

    __nv_bfloat16 *bhsh, *bhsl;
    cudaGetSymbolAddress((void**)&bhsh, g_hsh);
    cudaGetSymbolAddress((void**)&bhsl, g_hsl);

    const int smemA = (int)sizeof(SmemA);
    cudaFuncSetAttribute(chunk_outer, cudaFuncAttributeMaxDynamicSharedMemorySize, smemA);
    cudaFuncSetAttribute(attn_chunk,  cudaFuncAttributeMaxDynamicSharedMemorySize, ATT_SMEM);

    // bf16 hi/lo conversions
    conv_w<<<WROWS, 256>>>(Wq, Wk, Wv, Wo);
    conv_x<<<BT * HID / 1024, 256>>>(hs, bhsh, bhsl);

    // q/k/v projections on tensor cores (mma.sync)
    proj_mm<<<dim3(12, 8), 256>>>();

    // chunked causal linear attention
    chunk_outer<<<NTASK, 256, smemA>>>();
    prefix_kernel<<<dim3(NBH, 8), 256>>>();
    attn_chunk<<<NTASK, 256, ATT_SMEM>>>();

    // output projection on tensor cores
    out_mm<<<dim3(8, 8), 256>>>(out);
}

// round 16
// speedup vs baseline: 2.3837x; 1.1020x over previous
#include <cuda_runtime.h>
#include <cuda_bf16.h>
#include <cstdint>
#include <cstddef>

#define BB   2
#define TT   512
#define BT   1024
#define NH   16
#define FD   16
#define HD   64
#define HID  1024
#define DPHI 153
#define DPAD 160
#define CHK  64
#define NC   8
#define NBH  32
#define NTASK (NBH*NC)
#define EPSI 1e-12f

// ---- scratch ----
__device__ float g_q[BT * NH * FD];
__device__ float g_k[BT * NH * FD];
__device__ float g_v[BT * HID];
__device__ float g_G[NTASK * DPAD * HD];
__device__ float g_cs[NTASK * DPAD];
__device__ float g_Z[NTASK * DPAD];
__device__ __nv_bfloat16 g_Sh[NTASK * DPAD * HD];
__device__ __nv_bfloat16 g_Sl[NTASK * DPAD * HD];

__device__ __nv_bfloat16 g_hsh[BT * HID];
__device__ __nv_bfloat16 g_hsl[BT * HID];
__device__ __nv_bfloat16 g_yh[BT * HID];
__device__ __nv_bfloat16 g_yl[BT * HID];
#define WROWS 2560
__device__ __nv_bfloat16 g_wh[WROWS * HID];
__device__ __nv_bfloat16 g_wl[WROWS * HID];

__device__ __forceinline__ uint32_t s2u(const void* p) {
    uint32_t a;
    asm("{ .reg .u64 t; cvta.to.shared.u64 t, %1; cvt.u32.u64 %0, t; }"
        : "=r"(a) : "l"(p));
    return a;
}
__device__ __forceinline__ void ldm4(uint32_t& r0, uint32_t& r1,
                                     uint32_t& r2, uint32_t& r3, uint32_t a) {
    asm volatile("ldmatrix.sync.aligned.m8n8.x4.shared.b16 {%0,%1,%2,%3}, [%4];"
                 : "=r"(r0), "=r"(r1), "=r"(r2), "=r"(r3) : "r"(a));
}
__device__ __forceinline__ void ldm4t(uint32_t& r0, uint32_t& r1,
                                      uint32_t& r2, uint32_t& r3, uint32_t a) {
    asm volatile("ldmatrix.sync.aligned.m8n8.x4.trans.shared.b16 {%0,%1,%2,%3}, [%4];"
                 : "=r"(r0), "=r"(r1), "=r"(r2), "=r"(r3) : "r"(a));
}
__device__ __forceinline__ void mma16816(float* c, const uint32_t* a,
                                         const uint32_t* b) {
    asm volatile(
        "mma.sync.aligned.m16n8k16.row.col.f32.bf16.bf16.f32 "
        "{%0,%1,%2,%3}, {%4,%5,%6,%7}, {%8,%9}, {%0,%1,%2,%3};"
        : "+f"(c[0]), "+f"(c[1]), "+f"(c[2]), "+f"(c[3])
        : "r"(a[0]), "r"(a[1]), "r"(a[2]), "r"(a[3]), "r"(b[0]), "r"(b[1]));
}
__device__ __forceinline__ void bsplit(float v, __nv_bfloat16& h, __nv_bfloat16& l) {
    h = __float2bfloat16(v);
    l = __float2bfloat16(v - __bfloat162float(h));
}

// ============================================================================
// bf16-split conversion kernels
// ============================================================================
__global__ __launch_bounds__(256) void conv_x(
    const float* __restrict__ src, __nv_bfloat16* __restrict__ dh,
    __nv_bfloat16* __restrict__ dl)
{
    size_t base = (size_t)blockIdx.x * 1024 + threadIdx.x * 4;
    float4 x = *(const float4*)(src + base);
    __nv_bfloat16 h0, l0, h1, l1, h2, l2, h3, l3;
    bsplit(x.x, h0, l0); bsplit(x.y, h1, l1);
    bsplit(x.z, h2, l2); bsplit(x.w, h3, l3);
    __nv_bfloat162* H = (__nv_bfloat162*)(dh + base);
    __nv_bfloat162* L = (__nv_bfloat162*)(dl + base);
    H[0] = __nv_bfloat162(h0, h1); H[1] = __nv_bfloat162(h2, h3);
    L[0] = __nv_bfloat162(l0, l1); L[1] = __nv_bfloat162(l2, l3);
}

__global__ __launch_bounds__(256) void conv_w(
    const float* __restrict__ Wq, const float* __restrict__ Wk,
    const float* __restrict__ Wv, const float* __restrict__ Wo)
{
    const int r = blockIdx.x;
    const float* src;
    if (r < 256)       src = Wq + (size_t)r * HID;
    else if (r < 512)  src = Wk + (size_t)(r - 256) * HID;
    else if (r < 1536) src = Wv + (size_t)(r - 512) * HID;
    else               src = Wo + (size_t)(r - 1536) * HID;
    size_t base = (size_t)r * HID + threadIdx.x * 4;
    float4 x = *(const float4*)(src + threadIdx.x * 4);
    __nv_bfloat16 h0, l0, h1, l1, h2, l2, h3, l3;
    bsplit(x.x, h0, l0); bsplit(x.y, h1, l1);
    bsplit(x.z, h2, l2); bsplit(x.w, h3, l3);
    __nv_bfloat162* H = (__nv_bfloat162*)(g_wh + base);
    __nv_bfloat162* L = (__nv_bfloat162*)(g_wl + base);
    H[0] = __nv_bfloat162(h0, h1); H[1] = __nv_bfloat162(h2, h3);
    L[0] = __nv_bfloat162(l0, l1); L[1] = __nv_bfloat162(l2, l3);
}

// ============================================================================
// mma.sync bf16-split GEMM with register prefetch (pipeline depth 1).
// C[128,128] = A[128,1024] @ B[128,1024]^T, D = AhBh + AhBl + AlBh.
// ============================================================================
#define SROW 40

__device__ void mm128_core(
    const __nv_bfloat16* __restrict__ Ah, const __nv_bfloat16* __restrict__ Al,
    const __nv_bfloat16* __restrict__ Bh, const __nv_bfloat16* __restrict__ Bl,
    float* __restrict__ C, int ldc)
{
    __shared__ __align__(16) __nv_bfloat16 sAh[128 * SROW];
    __shared__ __align__(16) __nv_bfloat16 sAl[128 * SROW];
    __shared__ __align__(16) __nv_bfloat16 sBh[128 * SROW];
    __shared__ __align__(16) __nv_bfloat16 sBl[128 * SROW];

    const int tid = threadIdx.x;
    const int wid = tid >> 5, lane = tid & 31;
    const int warpM = (wid >> 2) * 64;
    const int warpN = (wid & 3) * 32;

    const int lt = lane >> 3, lr = lane & 7;
    const int aRow = lr + (lt & 1) * 8;
    const int aByte = (lt >> 1) * 16;
    const int bRow = lr + (lt >> 1) * 8;
    const int bByte = (lt & 1) * 16;

    const uint32_t uAh = s2u(sAh), uAl = s2u(sAl);
    const uint32_t uBh = s2u(sBh), uBl = s2u(sBl);

    const int r0c = tid >> 2, q0 = (tid & 3) * 8;
    const int r1c = (tid + 256) >> 2, q1 = ((tid + 256) & 3) * 8;

    float acc[4][4][4];
#pragma unroll
    for (int i = 0; i < 4; i++)
#pragma unroll
        for (int j = 0; j < 4; j++)
#pragma unroll
            for (int e = 0; e < 4; e++) acc[i][j][e] = 0.f;

    uint4 rg[8];
    // prologue load (kc = 0)
    {
        const int kb = 0;
        rg[0] = *(const uint4*)(Ah + (size_t)r0c * HID + kb + q0);
        rg[1] = *(const uint4*)(Ah + (size_t)r1c * HID + kb + q1);
        rg[2] = *(const uint4*)(Al + (size_t)r0c * HID + kb + q0);
        rg[3] = *(const uint4*)(Al + (size_t)r1c * HID + kb + q1);
        rg[4] = *(const uint4*)(Bh + (size_t)r0c * HID + kb + q0);
        rg[5] = *(const uint4*)(Bh + (size_t)r1c * HID + kb + q1);
        rg[6] = *(const uint4*)(Bl + (size_t)r0c * HID + kb + q0);
        rg[7] = *(const uint4*)(Bl + (size_t)r1c * HID + kb + q1);
    }

    for (int kc = 0; kc < HID / 32; kc++) {
        __syncthreads();   // previous compute done reading smem
        *(uint4*)(sAh + r0c * SROW + q0) = rg[0];
        *(uint4*)(sAh + r1c * SROW + q1) = rg[1];
        *(uint4*)(sAl + r0c * SROW + q0) = rg[2];
        *(uint4*)(sAl + r1c * SROW + q1) = rg[3];
        *(uint4*)(sBh + r0c * SROW + q0) = rg[4];
        *(uint4*)(sBh + r1c * SROW + q1) = rg[5];
        *(uint4*)(sBl + r0c * SROW + q0) = rg[6];
        *(uint4*)(sBl + r1c * SROW + q1) = rg[7];
        __syncthreads();

        uint4 nx[8];
        if (kc + 1 < HID / 32) {   // prefetch next chunk under compute
            const int kb = (kc + 1) * 32;
            nx[0] = *(const uint4*)(Ah + (size_t)r0c * HID + kb + q0);
            nx[1] = *(const uint4*)(Ah + (size_t)r1c * HID + kb + q1);
            nx[2] = *(const uint4*)(Al + (size_t)r0c * HID + kb + q0);
            nx[3] = *(const uint4*)(Al + (size_t)r1c * HID + kb + q1);
            nx[4] = *(const uint4*)(Bh + (size_t)r0c * HID + kb + q0);
            nx[5] = *(const uint4*)(Bh + (size_t)r1c * HID + kb + q1);
            nx[6] = *(const uint4*)(Bl + (size_t)r0c * HID + kb + q0);
            nx[7] = *(const uint4*)(Bl + (size_t)r1c * HID + kb + q1);
        }

#pragma unroll
        for (int s = 0; s < 2; s++) {
            const int sb = s * 32;
            uint32_t ah[4][4], bh[4][2], bl[4][2], al[4][4];

#pragma unroll
            for (int mi = 0; mi < 4; mi++)
                ldm4(ah[mi][0], ah[mi][1], ah[mi][2], ah[mi][3],
                     uAh + (warpM + mi * 16 + aRow) * 80 + sb + aByte);
#pragma unroll
            for (int g = 0; g < 2; g++)
                ldm4(bh[2 * g][0], bh[2 * g][1], bh[2 * g + 1][0], bh[2 * g + 1][1],
                     uBh + (warpN + g * 16 + bRow) * 80 + sb + bByte);
#pragma unroll
            for (int mi = 0; mi < 4; mi++)
#pragma unroll
                for (int ng = 0; ng < 4; ng++)
                    mma16816(acc[mi][ng], ah[mi], bh[ng]);

#pragma unroll
            for (int g = 0; g < 2; g++)
                ldm4(bl[2 * g][0], bl[2 * g][1], bl[2 * g + 1][0], bl[2 * g + 1][1],
                     uBl + (warpN + g * 16 + bRow) * 80 + sb + bByte);
#pragma unroll
            for (int mi = 0; mi < 4; mi++)
#pragma unroll
                for (int ng = 0; ng < 4; ng++)
                    mma16816(acc[mi][ng], ah[mi], bl[ng]);

#pragma unroll
            for (int mi = 0; mi < 4; mi++)
                ldm4(al[mi][0], al[mi][1], al[mi][2], al[mi][3],
                     uAl + (warpM + mi * 16 + aRow) * 80 + sb + aByte);
#pragma unroll
            for (int mi = 0; mi < 4; mi++)
#pragma unroll
                for (int ng = 0; ng < 4; ng++)
                    mma16816(acc[mi][ng], al[mi], bh[ng]);
        }

        if (kc + 1 < HID / 32) {
#pragma unroll
            for (int i = 0; i < 8; i++) rg[i] = nx[i];
        }
    }

    const int cr = lane >> 2, cc = (lane & 3) * 2;
#pragma unroll
    for (int mi = 0; mi < 4; mi++) {
#pragma unroll
        for (int ng = 0; ng < 4; ng++) {
            float* cp0 = C + (size_t)(warpM + mi * 16 + cr) * ldc
                           + warpN + ng * 8 + cc;
            float* cp1 = cp0 + 8 * ldc;
            cp0[0] = acc[mi][ng][0]; cp0[1] = acc[mi][ng][1];
            cp1[0] = acc[mi][ng][2]; cp1[1] = acc[mi][ng][3];
        }
    }
}

__global__ __launch_bounds__(256) void proj_mm()
{
    const int bx = blockIdx.x, by = blockIdx.y;
    float* C; int ldc, n0;
    if (bx < 2)      { C = g_q; ldc = NH * FD; n0 = bx * 128; }
    else if (bx < 4) { C = g_k; ldc = NH * FD; n0 = (bx - 2) * 128; }
    else             { C = g_v; ldc = HID;     n0 = (bx - 4) * 128; }
    const size_t ao = (size_t)by * 128 * HID;
    const size_t bo = (size_t)bx * 128 * HID;
    mm128_core(g_hsh + ao, g_hsl + ao, g_wh + bo, g_wl + bo,
               C + (size_t)by * 128 * ldc + n0, ldc);
}

__global__ __launch_bounds__(256) void out_mm(float* __restrict__ out)
{
    const int bx = blockIdx.x, by = blockIdx.y;
    const size_t ao = (size_t)by * 128 * HID;
    const size_t bo = (size_t)(1536 + bx * 128) * HID;
    mm128_core(g_yh + ao, g_yl + ao, g_wh + bo, g_wl + bo,
               out + (size_t)by * 128 * HID + bx * 128, HID);
}

// ============================================================================
// phi mapping
// ============================================================================
__device__ __forceinline__ void phi_map(int D, int& pi, int& pj, float& sc)
{
    pi = 16; pj = 16; sc = 0.f;
    if (D == 0)        { sc = 1.f; }
    else if (D < 17)   { pi = D - 1;  sc = 0.5f; }
    else if (D < 33)   { pi = D - 17; pj = pi; sc = 0.17677669529663687f; }
    else if (D < DPHI) {
        int pp = D - 33, i = 0;
        while (pp >= 15 - i) { pp -= 15 - i; i++; }
        pi = i; pj = i + 1 + pp; sc = 0.25f;
    }
}

// ============================================================================
// Kernel A v2 (tensor cores): G = phiK^T @ V (160x64x64) + colsum(phiK).
// A = phiK^T as [D][t] bf16-split rows (144B); B = V [t][d] via ldm4t.
// 8 warps: warpD = (wid>>2)*80 (5 m16 tiles), warpN = (wid&3)*16 (2 n8).
// ============================================================================
#define CO_R    0
#define CO_PH   4352
#define CO_PL   (CO_PH + DPAD * 72 * 2)     // 27392
#define CO_VH   (CO_PL + DPAD * 72 * 2)     // 50432
#define CO_VL   (CO_VH + CHK * 72 * 2)      // 59648
#define CO_SMEM (CO_VL + CHK * 72 * 2)      // 68864

__global__ __launch_bounds__(256) void chunk_outer()
{
    extern __shared__ char sm[];
    float* R = (float*)(sm + CO_R);                       // [64][17]
    __nv_bfloat16* Ph = (__nv_bfloat16*)(sm + CO_PH);     // [160][72]
    __nv_bfloat16* Pl = (__nv_bfloat16*)(sm + CO_PL);
    __nv_bfloat16* Vh = (__nv_bfloat16*)(sm + CO_VH);     // [64][72]
    __nv_bfloat16* Vl = (__nv_bfloat16*)(sm + CO_VL);

    const int task = blockIdx.x;
    const int bh = task >> 3, c = task & 7;
    const int b = bh >> 4, h = bh & 15, t0 = c * CHK;
    const int tid = threadIdx.x;
    const int wid = tid >> 5, lane = tid & 31;
    const int warpD = (wid >> 2) * 80;
    const int warpN = (wid & 3) * 16;
    const int lt = lane >> 3, lr = lane & 7;
    const int aRow = lr + (lt & 1) * 8;
    const int aByte = (lt >> 1) * 16;

    const uint32_t uPh = s2u(Ph), uPl = s2u(Pl);
    const uint32_t uVh = s2u(Vh), uVl = s2u(Vl);

    // raw k
    for (int e = tid; e < CHK * FD; e += 256) {
        int t = e >> 4, f = e & 15;
        R[t * 17 + f] = g_k[((size_t)(b * TT + t0 + t)) * (NH * FD) + h * FD + f];
    }
    if (tid < CHK) R[tid * 17 + 16] = 1.f;

    // V -> bf16 split [t][d]
    for (int e = tid; e < CHK * 16; e += 256) {
        int t = e >> 4, d0 = (e & 15) << 2;
        float4 v = *(const float4*)&g_v[((size_t)(b * TT + t0 + t)) * HID + h * HD + d0];
        __nv_bfloat16 hh, ll;
        bsplit(v.x, hh, ll); Vh[t * 72 + d0 + 0] = hh; Vl[t * 72 + d0 + 0] = ll;
        bsplit(v.y, hh, ll); Vh[t * 72 + d0 + 1] = hh; Vl[t * 72 + d0 + 1] = ll;
        bsplit(v.z, hh, ll); Vh[t * 72 + d0 + 2] = hh; Vl[t * 72 + d0 + 2] = ll;
        bsplit(v.w, hh, ll); Vh[t * 72 + d0 + 3] = hh; Vl[t * 72 + d0 + 3] = ll;
    }
    __syncthreads();

    // phiK -> bf16 split [D][t]
    if (tid < DPAD) {
        int pi, pj; float sc;
        phi_map(tid, pi, pj, sc);
        float cs = 0.f;
#pragma unroll 4
        for (int t = 0; t < CHK; t++) {
            float val = sc * R[t * 17 + pi] * R[t * 17 + pj];
            cs += val;
            __nv_bfloat16 hh, ll;
            bsplit(val, hh, ll);
            Ph[tid * 72 + t] = hh;
            Pl[tid * 72 + t] = ll;
        }
        g_cs[(size_t)task * DPAD + tid] = cs;   // fp32-exact colsum
    }
    __syncthreads();

    // G = P @ V via mma (3-product split)
    float acc[5][2][4];
#pragma unroll
    for (int mi = 0; mi < 5; mi++)
#pragma unroll
        for (int ng = 0; ng < 2; ng++)
#pragma unroll
            for (int e = 0; e < 4; e++) acc[mi][ng][e] = 0.f;

#pragma unroll
    for (int ks = 0; ks < 4; ks++) {
        const int kb = ks * 32;   // bytes into P rows
        const int kr = ks * 16;   // V row offset
        uint32_t ph[5][4], pl[5][4], vh[2][2], vl[2][2];
#pragma unroll
        for (int mi = 0; mi < 5; mi++) {
            ldm4(ph[mi][0], ph[mi][1], ph[mi][2], ph[mi][3],
                 uPh + (warpD + mi * 16 + aRow) * 144 + kb + aByte);
            ldm4(pl[mi][0], pl[mi][1], pl[mi][2], pl[mi][3],
                 uPl + (warpD + mi * 16 + aRow) * 144 + kb + aByte);
        }
        ldm4t(vh[0][0], vh[0][1], vh[1][0], vh[1][1],
              uVh + (kr + aRow) * 144 + warpN * 2 + aByte);
        ldm4t(vl[0][0], vl[0][1], vl[1][0], vl[1][1],
              uVl + (kr + aRow) * 144 + warpN * 2 + aByte);
#pragma unroll
        for (int mi = 0; mi < 5; mi++)
#pragma unroll
            for (int ng = 0; ng < 2; ng++) {
                mma16816(acc[mi][ng], ph[mi], vh[ng]);
                mma16816(acc[mi][ng], ph[mi], vl[ng]);
                mma16816(acc[mi][ng], pl[mi], vh[ng]);
            }
    }

    // epilogue: write G fp32
    const int cr = lane >> 2, cc = (lane & 3) * 2;
    float* Gp = g_G + (size_t)task * (DPAD * HD);
#pragma unroll
    for (int mi = 0; mi < 5; mi++) {
#pragma unroll
        for (int ng = 0; ng < 2; ng++) {
            int r0 = warpD + mi * 16 + cr;
            int c0 = warpN + ng * 8 + cc;
            int r1 = r0 + 8;
            Gp[r0 * HD + c0]     = acc[mi][ng][0];
            Gp[r0 * HD + c0 + 1] = acc[mi][ng][1];
            Gp[r1 * HD + c0]     = acc[mi][ng][2];
            Gp[r1 * HD + c0 + 1] = acc[mi][ng][3];
        }
    }
}

// ============================================================================
// Kernel B: exclusive prefix over chunks -> bf16 hi/lo S. grid (NBH, 8)
// ============================================================================
__global__ __launch_bounds__(256) void prefix_kernel()
{
    const int bh = blockIdx.x, z = blockIdx.y;
    const int tid = threadIdx.x;
    const size_t base = (size_t)bh * NC;
    const int e0 = z * (DPAD * HD / 8), e1 = e0 + (DPAD * HD / 8);

    for (int e = e0 + tid; e < e1; e += 256) {
        float carry = 0.f;
#pragma unroll
        for (int c = 0; c < NC; c++) {
            size_t idx = (base + c) * (DPAD * HD) + e;
            __nv_bfloat16 hh, ll;
            bsplit(carry, hh, ll);
            g_Sh[idx] = hh;
            g_Sl[idx] = ll;
            carry += g_G[idx];
        }
    }
    if (z == 0) {
        for (int e = tid; e < DPAD; e += 256) {
            float carry = 0.f;
#pragma unroll
            for (int c = 0; c < NC; c++) {
                size_t idx = (base + c) * DPAD + e;
                float v = g_cs[idx];
                g_Z[idx] = carry;
                carry += v;
            }
        }
    }
}

// ============================================================================
// Kernel C (r15, verified): tensor-core intra-chunk attention.
// ============================================================================
#define QROW 168
#define VROW 72
#define ATT_RQ   0
#define ATT_RK   4352
#define ATT_DEN  8704
#define ATT_QH   9216
#define ATT_QL   30720
#define ATT_KH   52224
#define ATT_KL   73728
#define ATT_VH   95232
#define ATT_VL   104448
#define ATT_AH   113664
#define ATT_AL   122880
#define ATT_SH   132096
#define ATT_SL   155136
#define ATT_SMEM 178176

__global__ __launch_bounds__(256) void attn_chunk()
{
    extern __shared__ char sm[];
    float* RQ  = (float*)(sm + ATT_RQ);
    float* RK  = (float*)(sm + ATT_RK);
    float* Den = (float*)(sm + ATT_DEN);
    __nv_bfloat16* Qh = (__nv_bfloat16*)(sm + ATT_QH);
    __nv_bfloat16* Ql = (__nv_bfloat16*)(sm + ATT_QL);
    __nv_bfloat16* Kh = (__nv_bfloat16*)(sm + ATT_KH);
    __nv_bfloat16* Kl = (__nv_bfloat16*)(sm + ATT_KL);
    __nv_bfloat16* Vh = (__nv_bfloat16*)(sm + ATT_VH);
    __nv_bfloat16* Vl = (__nv_bfloat16*)(sm + ATT_VL);
    __nv_bfloat16* Ah = (__nv_bfloat16*)(sm + ATT_AH);
    __nv_bfloat16* Al = (__nv_bfloat16*)(sm + ATT_AL);
    __nv_bfloat16* Sh = (__nv_bfloat16*)(sm + ATT_SH);
    __nv_bfloat16* Sl = (__nv_bfloat16*)(sm + ATT_SL);

    const int task = blockIdx.x;
    const int bh = task >> 3, c = task & 7;
    const int b = bh >> 4, h = bh & 15, t0 = c * CHK;
    const int tid = threadIdx.x;
    const int wid = tid >> 5, lane = tid & 31;
    const int warpM = (wid >> 2) * 32;
    const int warpN = (wid & 3) * 16;
    const int lt = lane >> 3, lr = lane & 7;
    const int aRow = lr + (lt & 1) * 8;
    const int aByte = (lt >> 1) * 16;
    const int bRow = lr + (lt >> 1) * 8;
    const int bByte = (lt & 1) * 16;

    const uint32_t uQh = s2u(Qh), uQl = s2u(Ql);
    const uint32_t uKh = s2u(Kh), uKl = s2u(Kl);
    const uint32_t uVh = s2u(Vh), uVl = s2u(Vl);
    const uint32_t uAh = s2u(Ah), uAl = s2u(Al);
    const uint32_t uSh = s2u(Sh), uSl = s2u(Sl);

    for (int e = tid; e < CHK * FD; e += 256) {
        int t = e >> 4, f = e & 15;
        size_t row = (size_t)(b * TT + t0 + t);
        RQ[t * 17 + f] = g_q[row * (NH * FD) + h * FD + f];
        RK[t * 17 + f] = g_k[row * (NH * FD) + h * FD + f];
    }
    if (tid < CHK) { RQ[tid * 17 + 16] = 1.f; RK[tid * 17 + 16] = 1.f; }

    for (int e = tid; e < CHK * 16; e += 256) {
        int t = e >> 4, d0 = (e & 15) << 2;
        float4 v = *(const float4*)&g_v[((size_t)(b * TT + t0 + t)) * HID + h * HD + d0];
        __nv_bfloat16 hh, ll;
        bsplit(v.x, hh, ll); Vh[t * VROW + d0 + 0] = hh; Vl[t * VROW + d0 + 0] = ll;
        bsplit(v.y, hh, ll); Vh[t * VROW + d0 + 1] = hh; Vl[t * VROW + d0 + 1] = ll;
        bsplit(v.z, hh, ll); Vh[t * VROW + d0 + 2] = hh; Vl[t * VROW + d0 + 2] = ll;
        bsplit(v.w, hh, ll); Vh[t * VROW + d0 + 3] = hh; Vl[t * VROW + d0 + 3] = ll;
    }

    {
        const size_t sbase = (size_t)task * (DPAD * HD);
        for (int cc2 = tid; cc2 < 1280; cc2 += 256) {
            int rowD = cc2 >> 3, off = (cc2 & 7) * 8;
            *(uint4*)(Sh + rowD * VROW + off) =
                *(const uint4*)(g_Sh + sbase + rowD * HD + off);
            *(uint4*)(Sl + rowD * VROW + off) =
                *(const uint4*)(g_Sl + sbase + rowD * HD + off);
        }
    }
    __syncthreads();

    {
        const int t = tid & 63, g = tid >> 6;
        const float* rq = RQ + t * 17;
        const float* rk = RK + t * 17;
        for (int D = g * 40; D < g * 40 + 40; D++) {
            int pi, pj; float sc;
            phi_map(D, pi, pj, sc);
            float vq = sc * rq[pi] * rq[pj];
            float vk = sc * rk[pi] * rk[pj];
            __nv_bfloat16 hh, ll;
            bsplit(vq, hh, ll); Qh[t * QROW + D] = hh; Ql[t * QROW + D] = ll;
            bsplit(vk, hh, ll); Kh[t * QROW + D] = hh; Kl[t * QROW + D] = ll;
        }
    }
    __syncthreads();

    float acc[2][2][4];
#pragma unroll
    for (int i = 0; i < 2; i++)
#pragma unroll
        for (int j = 0; j < 2; j++)
#pragma unroll
            for (int e = 0; e < 4; e++) acc[i][j][e] = 0.f;

#pragma unroll
    for (int ks = 0; ks < 10; ks++) {
        const int kb = ks * 32;
        uint32_t qh[2][4], ql[2][4], kh[2][2], kl[2][2];
#pragma unroll
        for (int mi = 0; mi < 2; mi++) {
            ldm4(qh[mi][0], qh[mi][1], qh[mi][2], qh[mi][3],
                 uQh + (warpM + mi * 16 + aRow) * 336 + kb + aByte);
            ldm4(ql[mi][0], ql[mi][1], ql[mi][2], ql[mi][3],
                 uQl + (warpM + mi * 16 + aRow) * 336 + kb + aByte);
        }
        ldm4(kh[0][0], kh[0][1], kh[1][0], kh[1][1],
             uKh + (warpN + bRow) * 336 + kb + bByte);
        ldm4(kl[0][0], kl[0][1], kl[1][0], kl[1][1],
             uKl + (warpN + bRow) * 336 + kb + bByte);
#pragma unroll
        for (int mi = 0; mi < 2; mi++)
#pragma unroll
            for (int ng = 0; ng < 2; ng++) {
                mma16816(acc[mi][ng], qh[mi], kh[ng]);
                mma16816(acc[mi][ng], qh[mi], kl[ng]);
                mma16816(acc[mi][ng], ql[mi], kh[ng]);
            }
    }

    const int cr = lane >> 2, cc = (lane & 3) * 2;
#pragma unroll
    for (int mi = 0; mi < 2; mi++) {
#pragma unroll
        for (int ng = 0; ng < 2; ng++) {
            int r0 = warpM + mi * 16 + cr;
            int c0 = warpN + ng * 8 + cc;
            float m0 = (c0     <= r0) ? acc[mi][ng][0] : 0.f;
            float m1 = (c0 + 1 <= r0) ? acc[mi][ng][1] : 0.f;
            int r1 = r0 + 8;
            float m2 = (c0     <= r1) ? acc[mi][ng][2] : 0.f;
            float m3 = (c0 + 1 <= r1) ? acc[mi][ng][3] : 0.f;
            __nv_bfloat16 h0, l0, h1, l1;
            bsplit(m0, h0, l0); bsplit(m1, h1, l1);
            *(__nv_bfloat162*)&Ah[r0 * VROW + c0] = __nv_bfloat162(h0, h1);
            *(__nv_bfloat162*)&Al[r0 * VROW + c0] = __nv_bfloat162(l0, l1);
            bsplit(m2, h0, l0); bsplit(m3, h1, l1);
            *(__nv_bfloat162*)&Ah[r1 * VROW + c0] = __nv_bfloat162(h0, h1);
            *(__nv_bfloat162*)&Al[r1 * VROW + c0] = __nv_bfloat162(l0, l1);
        }
    }
    __syncthreads();

    if (tid < CHK) {
        float den = EPSI;
        for (int j = 0; j < CHK; j++)
            den += __bfloat162float(Ah[tid * VROW + j]) +
                   __bfloat162float(Al[tid * VROW + j]);
        const float* Zp = g_Z + (size_t)task * DPAD;
        for (int D = 0; D < DPAD; D++) {
            float qv = __bfloat162float(Qh[tid * QROW + D]) +
                       __bfloat162float(Ql[tid * QROW + D]);
            den = fmaf(qv, __ldg(&Zp[D]), den);
        }
        Den[tid] = den;
    }

#pragma unroll
    for (int i = 0; i < 2; i++)
#pragma unroll
        for (int j = 0; j < 2; j++)
#pragma unroll
            for (int e = 0; e < 4; e++) acc[i][j][e] = 0.f;

#pragma unroll
    for (int ks = 0; ks < 4; ks++) {
        const int kr = ks * 16;
        uint32_t ah2[2][4], al2[2][4], bh2[2][2], bl2[2][2];
#pragma unroll
        for (int mi = 0; mi < 2; mi++) {
            ldm4(ah2[mi][0], ah2[mi][1], ah2[mi][2], ah2[mi][3],
                 uAh + (warpM + mi * 16 + aRow) * 144 + kr * 2 + aByte);
            ldm4(al2[mi][0], al2[mi][1], al2[mi][2], al2[mi][3],
                 uAl + (warpM + mi * 16 + aRow) * 144 + kr * 2 + aByte);
        }
        ldm4t(bh2[0][0], bh2[0][1], bh2[1][0], bh2[1][1],
              uVh + (kr + aRow) * 144 + warpN * 2 + aByte);
        ldm4t(bl2[0][0], bl2[0][1], bl2[1][0], bl2[1][1],
              uVl + (kr + aRow) * 144 + warpN * 2 + aByte);
#pragma unroll
        for (int mi = 0; mi < 2; mi++)
#pragma unroll
            for (int ng = 0; ng < 2; ng++) {
                mma16816(acc[mi][ng], ah2[mi], bh2[ng]);
                mma16816(acc[mi][ng], ah2[mi], bl2[ng]);
                mma16816(acc[mi][ng], al2[mi], bh2[ng]);
            }
    }

#pragma unroll
    for (int ks = 0; ks < 10; ks++) {
        const int kb = ks * 32;
        const int kr = ks * 16;
        uint32_t qh[2][4], ql[2][4], bh2[2][2], bl2[2][2];
#pragma unroll
        for (int mi = 0; mi < 2; mi++) {
            ldm4(qh[mi][0], qh[mi][1], qh[mi][2], qh[mi][3],
                 uQh + (warpM + mi * 16 + aRow) * 336 + kb + aByte);
            ldm4(ql[mi][0], ql[mi][1], ql[mi][2], ql[mi][3],
                 uQl + (warpM + mi * 16 + aRow) * 336 + kb + aByte);
        }
        ldm4t(bh2[0][0], bh2[0][1], bh2[1][0], bh2[1][1],
              uSh + (kr + aRow) * 144 + warpN * 2 + aByte);
        ldm4t(bl2[0][0], bl2[0][1], bl2[1][0], bl2[1][1],
              uSl + (kr + aRow) * 144 + warpN * 2 + aByte);
#pragma unroll
        for (int mi = 0; mi < 2; mi++)
#pragma unroll
            for (int ng = 0; ng < 2; ng++) {
                mma16816(acc[mi][ng], qh[mi], bh2[ng]);
                mma16816(acc[mi][ng], qh[mi], bl2[ng]);
                mma16816(acc[mi][ng], ql[mi], bh2[ng]);
            }
    }
    __syncthreads();

#pragma unroll
    for (int mi = 0; mi < 2; mi++) {
#pragma unroll
        for (int ng = 0; ng < 2; ng++) {
            int r0 = warpM + mi * 16 + cr;
            int c0 = warpN + ng * 8 + cc;
            int r1 = r0 + 8;
            float dn0 = 1.f / Den[r0];
            float dn1 = 1.f / Den[r1];
            float y0 = acc[mi][ng][0] * dn0, y1 = acc[mi][ng][1] * dn0;
            float y2 = acc[mi][ng][2] * dn1, y3 = acc[mi][ng][3] * dn1;
            size_t g0 = ((size_t)(b * TT + t0 + r0)) * HID + h * HD + c0;
            size_t g1 = ((size_t)(b * TT + t0 + r1)) * HID + h * HD + c0;
            __nv_bfloat16 h0, l0, h1, l1;
            bsplit(y0, h0, l0); bsplit(y1, h1, l1);
            *(__nv_bfloat162*)&g_yh[g0] = __nv_bfloat162(h0, h1);
            *(__nv_bfloat162*)&g_yl[g0] = __nv_bfloat162(l0, l1);
            bsplit(y2, h0, l0); bsplit(y3, h1, l1);
            *(__nv_bfloat162*)&g_yh[g1] = __nv_bfloat162(h0, h1);
            *(__nv_bfloat162*)&g_yl[g1] = __nv_bfloat162(l0, l1);
        }
    }
}

// ============================================================================
// kernel_launch
// ============================================================================
extern "C" void kernel_launch(void* const* d_in, const int* in_sizes, int n_in,
                              void* d_out, int out_size)
{
    const float* hs = (const float*)d_in[0];
    const float* Wq = (const float*)d_in[1];
    const float* Wk = (const float*)d_in[2];
    const float* Wv = (const float*)d_in[3];
    const float* Wo = (const float*)d_in[4];
    float* out = (float*)d_out;

    __nv_bfloat16 *bhsh, *bhsl;
    cudaGetSymbolAddress((void**)&bhsh, g_hsh);
    cudaGetSymbolAddress((void**)&bhsl, g_hsl);

    cudaFuncSetAttribute(chunk_outer, cudaFuncAttributeMaxDynamicSharedMemorySize, CO_SMEM);
    cudaFuncSetAttribute(attn_chunk,  cudaFuncAttributeMaxDynamicSharedMemorySize, ATT_SMEM);

    conv_w<<<WROWS, 256>>>(Wq, Wk, Wv, Wo);
    conv_x<<<BT * HID / 1024, 256>>>(hs, bhsh, bhsl);

    proj_mm<<<dim3(12, 8), 256>>>();

    chunk_outer<<<NTASK, 256, CO_SMEM>>>();
    prefix_kernel<<<dim3(NBH, 8), 256>>>();
    attn_chunk<<<NTASK, 256, ATT_SMEM>>>();

    out_mm<<<dim3(8, 8), 256>>>(out);
}

// round 17
// speedup vs baseline: 2.5831x; 1.0837x over previous
#include <cuda_runtime.h>
#include <cuda_bf16.h>
#include <cstdint>
#include <cstddef>

#define BB   2
#define TT   512
#define BT   1024
#define NH   16
#define FD   16
#define HD   64
#define HID  1024
#define DPHI 153
#define DPAD 160
#define CHK  64
#define NC   8
#define NBH  32
#define NTASK (NBH*NC)
#define EPSI 1e-12f

// ---- scratch ----
__device__ float g_q[BT * NH * FD];
__device__ float g_k[BT * NH * FD];
__device__ float g_v[BT * HID];
__device__ float g_cs[NTASK * DPAD];
__device__ float g_Z[NTASK * DPAD];
__device__ __nv_bfloat16 g_Gh[NTASK * DPAD * HD];
__device__ __nv_bfloat16 g_Gl[NTASK * DPAD * HD];
__device__ __nv_bfloat16 g_Sh[NTASK * DPAD * HD];
__device__ __nv_bfloat16 g_Sl[NTASK * DPAD * HD];

__device__ __nv_bfloat16 g_hsh[BT * HID];
__device__ __nv_bfloat16 g_hsl[BT * HID];
__device__ __nv_bfloat16 g_yh[BT * HID];
__device__ __nv_bfloat16 g_yl[BT * HID];
#define WROWS 2560
__device__ __nv_bfloat16 g_wh[WROWS * HID];
__device__ __nv_bfloat16 g_wl[WROWS * HID];

__device__ __forceinline__ uint32_t s2u(const void* p) {
    uint32_t a;
    asm("{ .reg .u64 t; cvta.to.shared.u64 t, %1; cvt.u32.u64 %0, t; }"
        : "=r"(a) : "l"(p));
    return a;
}
__device__ __forceinline__ void ldm4(uint32_t& r0, uint32_t& r1,
                                     uint32_t& r2, uint32_t& r3, uint32_t a) {
    asm volatile("ldmatrix.sync.aligned.m8n8.x4.shared.b16 {%0,%1,%2,%3}, [%4];"
                 : "=r"(r0), "=r"(r1), "=r"(r2), "=r"(r3) : "r"(a));
}
__device__ __forceinline__ void ldm4t(uint32_t& r0, uint32_t& r1,
                                      uint32_t& r2, uint32_t& r3, uint32_t a) {
    asm volatile("ldmatrix.sync.aligned.m8n8.x4.trans.shared.b16 {%0,%1,%2,%3}, [%4];"
                 : "=r"(r0), "=r"(r1), "=r"(r2), "=r"(r3) : "r"(a));
}
__device__ __forceinline__ void mma16816(float* c, const uint32_t* a,
                                         const uint32_t* b) {
    asm volatile(
        "mma.sync.aligned.m16n8k16.row.col.f32.bf16.bf16.f32 "
        "{%0,%1,%2,%3}, {%4,%5,%6,%7}, {%8,%9}, {%0,%1,%2,%3};"
        : "+f"(c[0]), "+f"(c[1]), "+f"(c[2]), "+f"(c[3])
        : "r"(a[0]), "r"(a[1]), "r"(a[2]), "r"(a[3]), "r"(b[0]), "r"(b[1]));
}
__device__ __forceinline__ void bsplit(float v, __nv_bfloat16& h, __nv_bfloat16& l) {
    h = __float2bfloat16(v);
    l = __float2bfloat16(v - __bfloat162float(h));
}

// ============================================================================
// phi mapping
// ============================================================================
__device__ __forceinline__ void phi_map(int D, int& pi, int& pj, float& sc)
{
    pi = 16; pj = 16; sc = 0.f;
    if (D == 0)        { sc = 1.f; }
    else if (D < 17)   { pi = D - 1;  sc = 0.5f; }
    else if (D < 33)   { pi = D - 17; pj = pi; sc = 0.17677669529663687f; }
    else if (D < DPHI) {
        int pp = D - 33, i = 0;
        while (pp >= 15 - i) { pp -= 15 - i; i++; }
        pi = i; pj = i + 1 + pp; sc = 0.25f;
    }
}

// ============================================================================
// merged bf16-split conversion: blocks [0,2560) weights, [2560,3584) hs
// ============================================================================
__global__ __launch_bounds__(256) void conv_all(
    const float* __restrict__ hs,
    const float* __restrict__ Wq, const float* __restrict__ Wk,
    const float* __restrict__ Wv, const float* __restrict__ Wo)
{
    const int r = blockIdx.x;
    const float* src;
    __nv_bfloat16 *dh, *dl;
    size_t base;
    if (r < WROWS) {
        if (r < 256)       src = Wq + (size_t)r * HID;
        else if (r < 512)  src = Wk + (size_t)(r - 256) * HID;
        else if (r < 1536) src = Wv + (size_t)(r - 512) * HID;
        else               src = Wo + (size_t)(r - 1536) * HID;
        dh = g_wh; dl = g_wl; base = (size_t)r * HID;
    } else {
        int rr = r - WROWS;
        src = hs + (size_t)rr * HID;
        dh = g_hsh; dl = g_hsl; base = (size_t)rr * HID;
    }
    size_t off = base + threadIdx.x * 4;
    float4 x = *(const float4*)(src + threadIdx.x * 4);
    __nv_bfloat16 h0, l0, h1, l1, h2, l2, h3, l3;
    bsplit(x.x, h0, l0); bsplit(x.y, h1, l1);
    bsplit(x.z, h2, l2); bsplit(x.w, h3, l3);
    __nv_bfloat162* H = (__nv_bfloat162*)(dh + off);
    __nv_bfloat162* L = (__nv_bfloat162*)(dl + off);
    H[0] = __nv_bfloat162(h0, h1); H[1] = __nv_bfloat162(h2, h3);
    L[0] = __nv_bfloat162(l0, l1); L[1] = __nv_bfloat162(l2, l3);
}

// ============================================================================
// mma.sync bf16-split GEMM, double-buffered smem + register prefetch.
// C[128,128] = A[128,1024] @ B[128,1024]^T, D = AhBh + AhBl + AlBh.
// Dynamic smem: 2 bufs x 4 arrays x 128x40 bf16 = 81920 B.
// ============================================================================
#define SROW 40
#define MM_TILE_B 10240            // bytes per array tile
#define MM_BUF_B  40960            // bytes per buffer (4 arrays)
#define MM_SMEM   81920

__device__ void mm128_core(
    const __nv_bfloat16* __restrict__ Ah, const __nv_bfloat16* __restrict__ Al,
    const __nv_bfloat16* __restrict__ Bh, const __nv_bfloat16* __restrict__ Bl,
    float* __restrict__ C, int ldc)
{
    extern __shared__ char dsm[];
    const uint32_t sbase = s2u(dsm);

    const int tid = threadIdx.x;
    const int wid = tid >> 5, lane = tid & 31;
    const int warpM = (wid >> 2) * 64;
    const int warpN = (wid & 3) * 32;

    const int lt = lane >> 3, lr = lane & 7;
    const int aRow = lr + (lt & 1) * 8;
    const int aByte = (lt >> 1) * 16;
    const int bRow = lr + (lt >> 1) * 8;
    const int bByte = (lt & 1) * 16;

    const int r0c = tid >> 2, q0 = (tid & 3) * 8;
    const int r1c = (tid + 256) >> 2, q1 = ((tid + 256) & 3) * 8;

    float acc[4][4][4];
#pragma unroll
    for (int i = 0; i < 4; i++)
#pragma unroll
        for (int j = 0; j < 4; j++)
#pragma unroll
            for (int e = 0; e < 4; e++) acc[i][j][e] = 0.f;

    uint4 rg[8];
    {
        rg[0] = *(const uint4*)(Ah + (size_t)r0c * HID + q0);
        rg[1] = *(const uint4*)(Ah + (size_t)r1c * HID + q1);
        rg[2] = *(const uint4*)(Al + (size_t)r0c * HID + q0);
        rg[3] = *(const uint4*)(Al + (size_t)r1c * HID + q1);
        rg[4] = *(const uint4*)(Bh + (size_t)r0c * HID + q0);
        rg[5] = *(const uint4*)(Bh + (size_t)r1c * HID + q1);
        rg[6] = *(const uint4*)(Bl + (size_t)r0c * HID + q0);
        rg[7] = *(const uint4*)(Bl + (size_t)r1c * HID + q1);
    }
    // prologue store -> buffer 0
    {
        __nv_bfloat16* s0 = (__nv_bfloat16*)(dsm);
#pragma unroll
        for (int arr = 0; arr < 4; arr++) {
            __nv_bfloat16* sp = s0 + arr * (MM_TILE_B / 2);
            *(uint4*)(sp + r0c * SROW + q0) = rg[2 * arr + 0];
            *(uint4*)(sp + r1c * SROW + q1) = rg[2 * arr + 1];
        }
    }
    __syncthreads();

    for (int kc = 0; kc < HID / 32; kc++) {
        const int cur = kc & 1;
        uint4 nx[8];
        if (kc + 1 < HID / 32) {
            const int kb = (kc + 1) * 32;
            nx[0] = *(const uint4*)(Ah + (size_t)r0c * HID + kb + q0);
            nx[1] = *(const uint4*)(Ah + (size_t)r1c * HID + kb + q1);
            nx[2] = *(const uint4*)(Al + (size_t)r0c * HID + kb + q0);
            nx[3] = *(const uint4*)(Al + (size_t)r1c * HID + kb + q1);
            nx[4] = *(const uint4*)(Bh + (size_t)r0c * HID + kb + q0);
            nx[5] = *(const uint4*)(Bh + (size_t)r1c * HID + kb + q1);
            nx[6] = *(const uint4*)(Bl + (size_t)r0c * HID + kb + q0);
            nx[7] = *(const uint4*)(Bl + (size_t)r1c * HID + kb + q1);
        }

        const uint32_t uAh = sbase + cur * MM_BUF_B;
        const uint32_t uAl = uAh + MM_TILE_B;
        const uint32_t uBh = uAh + 2 * MM_TILE_B;
        const uint32_t uBl = uAh + 3 * MM_TILE_B;

#pragma unroll
        for (int s = 0; s < 2; s++) {
            const int sb = s * 32;
            uint32_t ah[4][4], bh[4][2], bl[4][2], al[4][4];

#pragma unroll
            for (int mi = 0; mi < 4; mi++)
                ldm4(ah[mi][0], ah[mi][1], ah[mi][2], ah[mi][3],
                     uAh + (warpM + mi * 16 + aRow) * 80 + sb + aByte);
#pragma unroll
            for (int g = 0; g < 2; g++)
                ldm4(bh[2 * g][0], bh[2 * g][1], bh[2 * g + 1][0], bh[2 * g + 1][1],
                     uBh + (warpN + g * 16 + bRow) * 80 + sb + bByte);
#pragma unroll
            for (int mi = 0; mi < 4; mi++)
#pragma unroll
                for (int ng = 0; ng < 4; ng++)
                    mma16816(acc[mi][ng], ah[mi], bh[ng]);

#pragma unroll
            for (int g = 0; g < 2; g++)
                ldm4(bl[2 * g][0], bl[2 * g][1], bl[2 * g + 1][0], bl[2 * g + 1][1],
                     uBl + (warpN + g * 16 + bRow) * 80 + sb + bByte);
#pragma unroll
            for (int mi = 0; mi < 4; mi++)
#pragma unroll
                for (int ng = 0; ng < 4; ng++)
                    mma16816(acc[mi][ng], ah[mi], bl[ng]);

#pragma unroll
            for (int mi = 0; mi < 4; mi++)
                ldm4(al[mi][0], al[mi][1], al[mi][2], al[mi][3],
                     uAl + (warpM + mi * 16 + aRow) * 80 + sb + aByte);
#pragma unroll
            for (int mi = 0; mi < 4; mi++)
#pragma unroll
                for (int ng = 0; ng < 4; ng++)
                    mma16816(acc[mi][ng], al[mi], bh[ng]);
        }

        if (kc + 1 < HID / 32) {
            __nv_bfloat16* sn = (__nv_bfloat16*)(dsm + (cur ^ 1) * MM_BUF_B);
#pragma unroll
            for (int arr = 0; arr < 4; arr++) {
                __nv_bfloat16* sp = sn + arr * (MM_TILE_B / 2);
                *(uint4*)(sp + r0c * SROW + q0) = nx[2 * arr + 0];
                *(uint4*)(sp + r1c * SROW + q1) = nx[2 * arr + 1];
            }
        }
        __syncthreads();
    }

    const int cr = lane >> 2, cc = (lane & 3) * 2;
#pragma unroll
    for (int mi = 0; mi < 4; mi++) {
#pragma unroll
        for (int ng = 0; ng < 4; ng++) {
            float* cp0 = C + (size_t)(warpM + mi * 16 + cr) * ldc
                           + warpN + ng * 8 + cc;
            float* cp1 = cp0 + 8 * ldc;
            cp0[0] = acc[mi][ng][0]; cp0[1] = acc[mi][ng][1];
            cp1[0] = acc[mi][ng][2]; cp1[1] = acc[mi][ng][3];
        }
    }
}

__global__ __launch_bounds__(256) void proj_mm()
{
    const int bx = blockIdx.x, by = blockIdx.y;
    float* C; int ldc, n0;
    if (bx < 2)      { C = g_q; ldc = NH * FD; n0 = bx * 128; }
    else if (bx < 4) { C = g_k; ldc = NH * FD; n0 = (bx - 2) * 128; }
    else             { C = g_v; ldc = HID;     n0 = (bx - 4) * 128; }
    const size_t ao = (size_t)by * 128 * HID;
    const size_t bo = (size_t)bx * 128 * HID;
    mm128_core(g_hsh + ao, g_hsl + ao, g_wh + bo, g_wl + bo,
               C + (size_t)by * 128 * ldc + n0, ldc);
}

__global__ __launch_bounds__(256) void out_mm(float* __restrict__ out)
{
    const int bx = blockIdx.x, by = blockIdx.y;
    const size_t ao = (size_t)by * 128 * HID;
    const size_t bo = (size_t)(1536 + bx * 128) * HID;
    mm128_core(g_yh + ao, g_yl + ao, g_wh + bo, g_wl + bo,
               out + (size_t)by * 128 * HID + bx * 128, HID);
}

// ============================================================================
// Kernel A v3: G = phiK^T @ V (tensor cores) + colsum; table-driven phi,
// all-256-thread conversion; G written as bf16 hi/lo.
// ============================================================================
#define CO_R    0
#define CO_TPI  4352
#define CO_TPJ  4992
#define CO_TSC  5632
#define CO_PH   6272
#define CO_PL   (CO_PH + DPAD * 72 * 2)
#define CO_VH   (CO_PL + DPAD * 72 * 2)
#define CO_VL   (CO_VH + CHK * 72 * 2)
#define CO_SMEM (CO_VL + CHK * 72 * 2)

__global__ __launch_bounds__(256) void chunk_outer()
{
    extern __shared__ char sm[];
    float* R   = (float*)(sm + CO_R);
    int*   TPI = (int*)(sm + CO_TPI);
    int*   TPJ = (int*)(sm + CO_TPJ);
    float* TSC = (float*)(sm + CO_TSC);
    __nv_bfloat16* Ph = (__nv_bfloat16*)(sm + CO_PH);
    __nv_bfloat16* Pl = (__nv_bfloat16*)(sm + CO_PL);
    __nv_bfloat16* Vh = (__nv_bfloat16*)(sm + CO_VH);
    __nv_bfloat16* Vl = (__nv_bfloat16*)(sm + CO_VL);

    const int task = blockIdx.x;
    const int bh = task >> 3, c = task & 7;
    const int b = bh >> 4, h = bh & 15, t0 = c * CHK;
    const int tid = threadIdx.x;
    const int wid = tid >> 5, lane = tid & 31;
    const int warpD = (wid >> 2) * 80;
    const int warpN = (wid & 3) * 16;
    const int lt = lane >> 3, lr = lane & 7;
    const int aRow = lr + (lt & 1) * 8;
    const int aByte = (lt >> 1) * 16;

    const uint32_t uPh = s2u(Ph), uPl = s2u(Pl);
    const uint32_t uVh = s2u(Vh), uVl = s2u(Vl);

    // stage raw k + tables
    for (int e = tid; e < CHK * FD; e += 256) {
        int t = e >> 4, f = e & 15;
        R[t * 17 + f] = g_k[((size_t)(b * TT + t0 + t)) * (NH * FD) + h * FD + f];
    }
    if (tid < CHK) R[tid * 17 + 16] = 1.f;
    if (tid < DPAD) {
        int pi, pj; float sc;
        phi_map(tid, pi, pj, sc);
        TPI[tid] = pi; TPJ[tid] = pj; TSC[tid] = sc;
    }

    // V -> bf16 split [t][d]
    for (int e = tid; e < CHK * 16; e += 256) {
        int t = e >> 4, d0 = (e & 15) << 2;
        float4 v = *(const float4*)&g_v[((size_t)(b * TT + t0 + t)) * HID + h * HD + d0];
        __nv_bfloat16 hh, ll;
        bsplit(v.x, hh, ll); Vh[t * 72 + d0 + 0] = hh; Vl[t * 72 + d0 + 0] = ll;
        bsplit(v.y, hh, ll); Vh[t * 72 + d0 + 1] = hh; Vl[t * 72 + d0 + 1] = ll;
        bsplit(v.z, hh, ll); Vh[t * 72 + d0 + 2] = hh; Vl[t * 72 + d0 + 2] = ll;
        bsplit(v.w, hh, ll); Vh[t * 72 + d0 + 3] = hh; Vl[t * 72 + d0 + 3] = ll;
    }
    __syncthreads();

    // phiK split, all 256 threads: t fixed per thread, D strided by 4
    for (int e = tid; e < DPAD * CHK; e += 256) {
        int D = e >> 6, t = e & 63;
        float val = TSC[D] * R[t * 17 + TPI[D]] * R[t * 17 + TPJ[D]];
        __nv_bfloat16 hh, ll;
        bsplit(val, hh, ll);
        Ph[D * 72 + t] = hh;
        Pl[D * 72 + t] = ll;
    }
    __syncthreads();

    // colsum per D (fp32 from hi+lo; error ~2^-17 relative)
    if (tid < DPAD) {
        float cs = 0.f;
        const uint4* ph4 = (const uint4*)(Ph + tid * 72);
        const uint4* pl4 = (const uint4*)(Pl + tid * 72);
#pragma unroll
        for (int i = 0; i < 8; i++) {
            uint4 vh = ph4[i], vl = pl4[i];
            const __nv_bfloat162* h2 = (const __nv_bfloat162*)&vh;
            const __nv_bfloat162* l2 = (const __nv_bfloat162*)&vl;
#pragma unroll
            for (int j = 0; j < 4; j++) {
                float2 a = __bfloat1622float2(h2[j]);
                float2 bq = __bfloat1622float2(l2[j]);
                cs += a.x + a.y + bq.x + bq.y;
            }
        }
        g_cs[(size_t)task * DPAD + tid] = cs;
    }

    // G = P @ V via mma (3-product split)
    float acc[5][2][4];
#pragma unroll
    for (int mi = 0; mi < 5; mi++)
#pragma unroll
        for (int ng = 0; ng < 2; ng++)
#pragma unroll
            for (int e = 0; e < 4; e++) acc[mi][ng][e] = 0.f;

#pragma unroll
    for (int ks = 0; ks < 4; ks++) {
        const int kb = ks * 32;
        const int kr = ks * 16;
        uint32_t ph[5][4], pl[5][4], vh[2][2], vl[2][2];
#pragma unroll
        for (int mi = 0; mi < 5; mi++) {
            ldm4(ph[mi][0], ph[mi][1], ph[mi][2], ph[mi][3],
                 uPh + (warpD + mi * 16 + aRow) * 144 + kb + aByte);
            ldm4(pl[mi][0], pl[mi][1], pl[mi][2], pl[mi][3],
                 uPl + (warpD + mi * 16 + aRow) * 144 + kb + aByte);
        }
        ldm4t(vh[0][0], vh[0][1], vh[1][0], vh[1][1],
              uVh + (kr + aRow) * 144 + warpN * 2 + aByte);
        ldm4t(vl[0][0], vl[0][1], vl[1][0], vl[1][1],
              uVl + (kr + aRow) * 144 + warpN * 2 + aByte);
#pragma unroll
        for (int mi = 0; mi < 5; mi++)
#pragma unroll
            for (int ng = 0; ng < 2; ng++) {
                mma16816(acc[mi][ng], ph[mi], vh[ng]);
                mma16816(acc[mi][ng], ph[mi], vl[ng]);
                mma16816(acc[mi][ng], pl[mi], vh[ng]);
            }
    }

    // epilogue: G as bf16 hi/lo
    const int cr = lane >> 2, cc = (lane & 3) * 2;
    const size_t gbase = (size_t)task * (DPAD * HD);
#pragma unroll
    for (int mi = 0; mi < 5; mi++) {
#pragma unroll
        for (int ng = 0; ng < 2; ng++) {
            int r0 = warpD + mi * 16 + cr;
            int c0 = warpN + ng * 8 + cc;
            int r1 = r0 + 8;
            __nv_bfloat16 h0, l0, h1, l1;
            bsplit(acc[mi][ng][0], h0, l0); bsplit(acc[mi][ng][1], h1, l1);
            *(__nv_bfloat162*)&g_Gh[gbase + r0 * HD + c0] = __nv_bfloat162(h0, h1);
            *(__nv_bfloat162*)&g_Gl[gbase + r0 * HD + c0] = __nv_bfloat162(l0, l1);
            bsplit(acc[mi][ng][2], h0, l0); bsplit(acc[mi][ng][3], h1, l1);
            *(__nv_bfloat162*)&g_Gh[gbase + r1 * HD + c0] = __nv_bfloat162(h0, h1);
            *(__nv_bfloat162*)&g_Gl[gbase + r1 * HD + c0] = __nv_bfloat162(l0, l1);
        }
    }
}

// ============================================================================
// Kernel B: exclusive prefix over chunks -> bf16 hi/lo S. grid (NBH, 8)
// ============================================================================
__global__ __launch_bounds__(256) void prefix_kernel()
{
    const int bh = blockIdx.x, z = blockIdx.y;
    const int tid = threadIdx.x;
    const size_t base = (size_t)bh * NC;
    const int e0 = z * (DPAD * HD / 8), e1 = e0 + (DPAD * HD / 8);

    for (int e = e0 + tid; e < e1; e += 256) {
        float carry = 0.f;
#pragma unroll
        for (int c = 0; c < NC; c++) {
            size_t idx = (base + c) * (DPAD * HD) + e;
            __nv_bfloat16 hh, ll;
            bsplit(carry, hh, ll);
            g_Sh[idx] = hh;
            g_Sl[idx] = ll;
            carry += __bfloat162float(g_Gh[idx]) + __bfloat162float(g_Gl[idx]);
        }
    }
    if (z == 0) {
        for (int e = tid; e < DPAD; e += 256) {
            float carry = 0.f;
#pragma unroll
            for (int c = 0; c < NC; c++) {
                size_t idx = (base + c) * DPAD + e;
                float v = g_cs[idx];
                g_Z[idx] = carry;
                carry += v;
            }
        }
    }
}

// ============================================================================
// Kernel C: tensor-core intra-chunk attention; table-driven phi; 4-way
// parallel denominator.
// ============================================================================
#define QROW 168
#define VROW 72
#define ATT_RQ    0
#define ATT_RK    4352
#define ATT_DENP  8704
#define ATT_TPI   9728
#define ATT_TPJ   10368
#define ATT_TSC   11008
#define ATT_QH    11648
#define ATT_QL    (ATT_QH + 21504)
#define ATT_KH    (ATT_QL + 21504)
#define ATT_KL    (ATT_KH + 21504)
#define ATT_VH    (ATT_KL + 21504)
#define ATT_VL    (ATT_VH + 9216)
#define ATT_AH    (ATT_VL + 9216)
#define ATT_AL    (ATT_AH + 9216)
#define ATT_SH    (ATT_AL + 9216)
#define ATT_SL    (ATT_SH + 23040)
#define ATT_SMEM  (ATT_SL + 23040)

__global__ __launch_bounds__(256) void attn_chunk()
{
    extern __shared__ char sm[];
    float* RQ   = (float*)(sm + ATT_RQ);
    float* RK   = (float*)(sm + ATT_RK);
    float* DenP = (float*)(sm + ATT_DENP);    // [4][64]
    int*   TPI  = (int*)(sm + ATT_TPI);
    int*   TPJ  = (int*)(sm + ATT_TPJ);
    float* TSC  = (float*)(sm + ATT_TSC);
    __nv_bfloat16* Qh = (__nv_bfloat16*)(sm + ATT_QH);
    __nv_bfloat16* Ql = (__nv_bfloat16*)(sm + ATT_QL);
    __nv_bfloat16* Kh = (__nv_bfloat16*)(sm + ATT_KH);
    __nv_bfloat16* Kl = (__nv_bfloat16*)(sm + ATT_KL);
    __nv_bfloat16* Vh = (__nv_bfloat16*)(sm + ATT_VH);
    __nv_bfloat16* Vl = (__nv_bfloat16*)(sm + ATT_VL);
    __nv_bfloat16* Ah = (__nv_bfloat16*)(sm + ATT_AH);
    __nv_bfloat16* Al = (__nv_bfloat16*)(sm + ATT_AL);
    __nv_bfloat16* Sh = (__nv_bfloat16*)(sm + ATT_SH);
    __nv_bfloat16* Sl = (__nv_bfloat16*)(sm + ATT_SL);

    const int task = blockIdx.x;
    const int bh = task >> 3, c = task & 7;
    const int b = bh >> 4, h = bh & 15, t0 = c * CHK;
    const int tid = threadIdx.x;
    const int wid = tid >> 5, lane = tid & 31;
    const int warpM = (wid >> 2) * 32;
    const int warpN = (wid & 3) * 16;
    const int lt = lane >> 3, lr = lane & 7;
    const int aRow = lr + (lt & 1) * 8;
    const int aByte = (lt >> 1) * 16;
    const int bRow = lr + (lt >> 1) * 8;
    const int bByte = (lt & 1) * 16;

    const uint32_t uQh = s2u(Qh), uQl = s2u(Ql);
    const uint32_t uKh = s2u(Kh), uKl = s2u(Kl);
    const uint32_t uVh = s2u(Vh), uVl = s2u(Vl);
    const uint32_t uAh = s2u(Ah), uAl = s2u(Al);
    const uint32_t uSh = s2u(Sh), uSl = s2u(Sl);

    for (int e = tid; e < CHK * FD; e += 256) {
        int t = e >> 4, f = e & 15;
        size_t row = (size_t)(b * TT + t0 + t);
        RQ[t * 17 + f] = g_q[row * (NH * FD) + h * FD + f];
        RK[t * 17 + f] = g_k[row * (NH * FD) + h * FD + f];
    }
    if (tid < CHK) { RQ[tid * 17 + 16] = 1.f; RK[tid * 17 + 16] = 1.f; }
    if (tid < DPAD) {
        int pi, pj; float sc;
        phi_map(tid, pi, pj, sc);
        TPI[tid] = pi; TPJ[tid] = pj; TSC[tid] = sc;
    }

    for (int e = tid; e < CHK * 16; e += 256) {
        int t = e >> 4, d0 = (e & 15) << 2;
        float4 v = *(const float4*)&g_v[((size_t)(b * TT + t0 + t)) * HID + h * HD + d0];
        __nv_bfloat16 hh, ll;
        bsplit(v.x, hh, ll); Vh[t * VROW + d0 + 0] = hh; Vl[t * VROW + d0 + 0] = ll;
        bsplit(v.y, hh, ll); Vh[t * VROW + d0 + 1] = hh; Vl[t * VROW + d0 + 1] = ll;
        bsplit(v.z, hh, ll); Vh[t * VROW + d0 + 2] = hh; Vl[t * VROW + d0 + 2] = ll;
        bsplit(v.w, hh, ll); Vh[t * VROW + d0 + 3] = hh; Vl[t * VROW + d0 + 3] = ll;
    }

    {
        const size_t sbase = (size_t)task * (DPAD * HD);
        for (int cc2 = tid; cc2 < 1280; cc2 += 256) {
            int rowD = cc2 >> 3, off = (cc2 & 7) * 8;
            *(uint4*)(Sh + rowD * VROW + off) =
                *(const uint4*)(g_Sh + sbase + rowD * HD + off);
            *(uint4*)(Sl + rowD * VROW + off) =
                *(const uint4*)(g_Sl + sbase + rowD * HD + off);
        }
    }
    __syncthreads();

    // table-driven phi split: t fixed per thread, D strided by 4
    for (int e = tid; e < DPAD * CHK; e += 256) {
        int D = e >> 6, t = e & 63;
        float sc = TSC[D];
        int pi = TPI[D], pj = TPJ[D];
        float vq = sc * RQ[t * 17 + pi] * RQ[t * 17 + pj];
        float vk = sc * RK[t * 17 + pi] * RK[t * 17 + pj];
        __nv_bfloat16 hh, ll;
        bsplit(vq, hh, ll); Qh[t * QROW + D] = hh; Ql[t * QROW + D] = ll;
        bsplit(vk, hh, ll); Kh[t * QROW + D] = hh; Kl[t * QROW + D] = ll;
    }
    __syncthreads();

    float acc[2][2][4];
#pragma unroll
    for (int i = 0; i < 2; i++)
#pragma unroll
        for (int j = 0; j < 2; j++)
#pragma unroll
            for (int e = 0; e < 4; e++) acc[i][j][e] = 0.f;

#pragma unroll
    for (int ks = 0; ks < 10; ks++) {
        const int kb = ks * 32;
        uint32_t qh[2][4], ql[2][4], kh[2][2], kl[2][2];
#pragma unroll
        for (int mi = 0; mi < 2; mi++) {
            ldm4(qh[mi][0], qh[mi][1], qh[mi][2], qh[mi][3],
                 uQh + (warpM + mi * 16 + aRow) * 336 + kb + aByte);
            ldm4(ql[mi][0], ql[mi][1], ql[mi][2], ql[mi][3],
                 uQl + (warpM + mi * 16 + aRow) * 336 + kb + aByte);
        }
        ldm4(kh[0][0], kh[0][1], kh[1][0], kh[1][1],
             uKh + (warpN + bRow) * 336 + kb + bByte);
        ldm4(kl[0][0], kl[0][1], kl[1][0], kl[1][1],
             uKl + (warpN + bRow) * 336 + kb + bByte);
#pragma unroll
        for (int mi = 0; mi < 2; mi++)
#pragma unroll
            for (int ng = 0; ng < 2; ng++) {
                mma16816(acc[mi][ng], qh[mi], kh[ng]);
                mma16816(acc[mi][ng], qh[mi], kl[ng]);
                mma16816(acc[mi][ng], ql[mi], kh[ng]);
            }
    }

    const int cr = lane >> 2, cc = (lane & 3) * 2;
#pragma unroll
    for (int mi = 0; mi < 2; mi++) {
#pragma unroll
        for (int ng = 0; ng < 2; ng++) {
            int r0 = warpM + mi * 16 + cr;
            int c0 = warpN + ng * 8 + cc;
            float m0 = (c0     <= r0) ? acc[mi][ng][0] : 0.f;
            float m1 = (c0 + 1 <= r0) ? acc[mi][ng][1] : 0.f;
            int r1 = r0 + 8;
            float m2 = (c0     <= r1) ? acc[mi][ng][2] : 0.f;
            float m3 = (c0 + 1 <= r1) ? acc[mi][ng][3] : 0.f;
            __nv_bfloat16 h0, l0, h1, l1;
            bsplit(m0, h0, l0); bsplit(m1, h1, l1);
            *(__nv_bfloat162*)&Ah[r0 * VROW + c0] = __nv_bfloat162(h0, h1);
            *(__nv_bfloat162*)&Al[r0 * VROW + c0] = __nv_bfloat162(l0, l1);
            bsplit(m2, h0, l0); bsplit(m3, h1, l1);
            *(__nv_bfloat162*)&Ah[r1 * VROW + c0] = __nv_bfloat162(h0, h1);
            *(__nv_bfloat162*)&Al[r1 * VROW + c0] = __nv_bfloat162(l0, l1);
        }
    }
    __syncthreads();

    // 4-way parallel denominator partials: part = tid>>6, t = tid&63
    {
        const int part = tid >> 6, t = tid & 63;
        float dp = 0.f;
        const int j0 = part * 16;
        const uint4* ah4 = (const uint4*)(Ah + t * VROW + j0);
        const uint4* al4 = (const uint4*)(Al + t * VROW + j0);
#pragma unroll
        for (int i = 0; i < 2; i++) {
            uint4 vh = ah4[i], vl = al4[i];
            const __nv_bfloat162* h2 = (const __nv_bfloat162*)&vh;
            const __nv_bfloat162* l2 = (const __nv_bfloat162*)&vl;
#pragma unroll
            for (int j = 0; j < 4; j++) {
                float2 a = __bfloat1622float2(h2[j]);
                float2 bq = __bfloat1622float2(l2[j]);
                dp += a.x + a.y + bq.x + bq.y;
            }
        }
        const float* Zp = g_Z + (size_t)task * DPAD;
        for (int D = part * 40; D < part * 40 + 40; D++) {
            float qv = __bfloat162float(Qh[t * QROW + D]) +
                       __bfloat162float(Ql[t * QROW + D]);
            dp = fmaf(qv, __ldg(&Zp[D]), dp);
        }
        DenP[part * 64 + t] = dp;
    }

#pragma unroll
    for (int i = 0; i < 2; i++)
#pragma unroll
        for (int j = 0; j < 2; j++)
#pragma unroll
            for (int e = 0; e < 4; e++) acc[i][j][e] = 0.f;

#pragma unroll
    for (int ks = 0; ks < 4; ks++) {
        const int kr = ks * 16;
        uint32_t ah2[2][4], al2[2][4], bh2[2][2], bl2[2][2];
#pragma unroll
        for (int mi = 0; mi < 2; mi++) {
            ldm4(ah2[mi][0], ah2[mi][1], ah2[mi][2], ah2[mi][3],
                 uAh + (warpM + mi * 16 + aRow) * 144 + kr * 2 + aByte);
            ldm4(al2[mi][0], al2[mi][1], al2[mi][2], al2[mi][3],
                 uAl + (warpM + mi * 16 + aRow) * 144 + kr * 2 + aByte);
        }
        ldm4t(bh2[0][0], bh2[0][1], bh2[1][0], bh2[1][1],
              uVh + (kr + aRow) * 144 + warpN * 2 + aByte);
        ldm4t(bl2[0][0], bl2[0][1], bl2[1][0], bl2[1][1],
              uVl + (kr + aRow) * 144 + warpN * 2 + aByte);
#pragma unroll
        for (int mi = 0; mi < 2; mi++)
#pragma unroll
            for (int ng = 0; ng < 2; ng++) {
                mma16816(acc[mi][ng], ah2[mi], bh2[ng]);
                mma16816(acc[mi][ng], ah2[mi], bl2[ng]);
                mma16816(acc[mi][ng], al2[mi], bh2[ng]);
            }
    }

#pragma unroll
    for (int ks = 0; ks < 10; ks++) {
        const int kb = ks * 32;
        const int kr = ks * 16;
        uint32_t qh[2][4], ql[2][4], bh2[2][2], bl2[2][2];
#pragma unroll
        for (int mi = 0; mi < 2; mi++) {
            ldm4(qh[mi][0], qh[mi][1], qh[mi][2], qh[mi][3],
                 uQh + (warpM + mi * 16 + aRow) * 336 + kb + aByte);
            ldm4(ql[mi][0], ql[mi][1], ql[mi][2], ql[mi][3],
                 uQl + (warpM + mi * 16 + aRow) * 336 + kb + aByte);
        }
        ldm4t(bh2[0][0], bh2[0][1], bh2[1][0], bh2[1][1],
              uSh + (kr + aRow) * 144 + warpN * 2 + aByte);
        ldm4t(bl2[0][0], bl2[0][1], bl2[1][0], bl2[1][1],
              uSl + (kr + aRow) * 144 + warpN * 2 + aByte);
#pragma unroll
        for (int mi = 0; mi < 2; mi++)
#pragma unroll
            for (int ng = 0; ng < 2; ng++) {
                mma16816(acc[mi][ng], qh[mi], bh2[ng]);
                mma16816(acc[mi][ng], qh[mi], bl2[ng]);
                mma16816(acc[mi][ng], ql[mi], bh2[ng]);
            }
    }
    __syncthreads();   // DenP ready

#pragma unroll
    for (int mi = 0; mi < 2; mi++) {
#pragma unroll
        for (int ng = 0; ng < 2; ng++) {
            int r0 = warpM + mi * 16 + cr;
            int c0 = warpN + ng * 8 + cc;
            int r1 = r0 + 8;
            float dn0 = 1.f / (EPSI + DenP[r0] + DenP[64 + r0] +
                               DenP[128 + r0] + DenP[192 + r0]);
            float dn1 = 1.f / (EPSI + DenP[r1] + DenP[64 + r1] +
                               DenP[128 + r1] + DenP[192 + r1]);
            float y0 = acc[mi][ng][0] * dn0, y1 = acc[mi][ng][1] * dn0;
            float y2 = acc[mi][ng][2] * dn1, y3 = acc[mi][ng][3] * dn1;
            size_t g0 = ((size_t)(b * TT + t0 + r0)) * HID + h * HD + c0;
            size_t g1 = ((size_t)(b * TT + t0 + r1)) * HID + h * HD + c0;
            __nv_bfloat16 h0, l0, h1, l1;
            bsplit(y0, h0, l0); bsplit(y1, h1, l1);
            *(__nv_bfloat162*)&g_yh[g0] = __nv_bfloat162(h0, h1);
            *(__nv_bfloat162*)&g_yl[g0] = __nv_bfloat162(l0, l1);
            bsplit(y2, h0, l0); bsplit(y3, h1, l1);
            *(__nv_bfloat162*)&g_yh[g1] = __nv_bfloat162(h0, h1);
            *(__nv_bfloat162*)&g_yl[g1] = __nv_bfloat162(l0, l1);
        }
    }
}

// ============================================================================
// kernel_launch
// ============================================================================
extern "C" void kernel_launch(void* const* d_in, const int* in_sizes, int n_in,
                              void* d_out, int out_size)
{
    const float* hs = (const float*)d_in[0];
    const float* Wq = (const float*)d_in[1];
    const float* Wk = (const float*)d_in[2];
    const float* Wv = (const float*)d_in[3];
    const float* Wo = (const float*)d_in[4];
    float* out = (float*)d_out;

    cudaFuncSetAttribute(proj_mm, cudaFuncAttributeMaxDynamicSharedMemorySize, MM_SMEM);
    cudaFuncSetAttribute(out_mm,  cudaFuncAttributeMaxDynamicSharedMemorySize, MM_SMEM);
    cudaFuncSetAttribute(chunk_outer, cudaFuncAttributeMaxDynamicSharedMemorySize, CO_SMEM);
    cudaFuncSetAttribute(attn_chunk,  cudaFuncAttributeMaxDynamicSharedMemorySize, ATT_SMEM);

    conv_all<<<WROWS + BT, 256>>>(hs, Wq, Wk, Wv, Wo);

    proj_mm<<<dim3(12, 8), 256, MM_SMEM>>>();

    chunk_outer<<<NTASK, 256, CO_SMEM>>>();
    prefix_kernel<<<dim3(NBH, 8), 256>>>();
    attn_chunk<<<NTASK, 256, ATT_SMEM>>>();

    out_mm<<<dim3(8, 8), 256, MM_SMEM>>>(out);
}